// round 2
// baseline (speedup 1.0000x reference)
#include <cuda_runtime.h>
#include <cstdint>

#define BATCH 16
#define DIM   256
#define NPOS  4096   // 64*64
#define HH    64
#define WW    64

// ---------------- scratch (no allocation allowed) ----------------
__device__ float g_qkv[(size_t)BATCH * 768 * NPOS];   // q rows 0-255, k 256-511, v 512-767
__device__ float g_y[(size_t)BATCH * DIM * NPOS];     // dw + normalized attn
__device__ float g_vkT[(size_t)BATCH * DIM * DIM];
__device__ float g_kmean[BATCH * DIM];

// ---------------- generic tiled SGEMM: C[b] = A[M,K] * X[b][K,Nn] + bias ----------------
__global__ void gemm64_kernel(const float* __restrict__ A, const float* __restrict__ X,
                              const float* __restrict__ bias, float* __restrict__ C,
                              int K, int Nn, long long xStrideB, long long cStrideB)
{
    int b = blockIdx.z;
    const float* Xb = X + (long long)b * xStrideB;
    float* Cb = C + (long long)b * cStrideB;
    int m0 = blockIdx.y * 64, n0 = blockIdx.x * 64;
    __shared__ float As[16][65];
    __shared__ float Bs[16][65];
    int tid = threadIdx.x;
    int tr = tid >> 4, tc = tid & 15;
    float acc[4][4] = {};
    for (int k0 = 0; k0 < K; k0 += 16) {
        for (int idx = tid; idx < 1024; idx += 256) {
            int r = idx >> 4, c = idx & 15;
            As[c][r] = A[(m0 + r) * K + k0 + c];
        }
        for (int idx = tid; idx < 1024; idx += 256) {
            int r = idx >> 6, c = idx & 63;
            Bs[r][c] = Xb[(long long)(k0 + r) * Nn + n0 + c];
        }
        __syncthreads();
#pragma unroll
        for (int kk = 0; kk < 16; ++kk) {
            float a[4], bb[4];
#pragma unroll
            for (int i = 0; i < 4; ++i) a[i] = As[kk][tr * 4 + i];
#pragma unroll
            for (int j = 0; j < 4; ++j) bb[j] = Bs[kk][tc * 4 + j];
#pragma unroll
            for (int i = 0; i < 4; ++i)
#pragma unroll
                for (int j = 0; j < 4; ++j) acc[i][j] += a[i] * bb[j];
        }
        __syncthreads();
    }
#pragma unroll
    for (int i = 0; i < 4; ++i) {
        float bv = bias ? bias[m0 + tr * 4 + i] : 0.f;
#pragma unroll
        for (int j = 0; j < 4; ++j)
            Cb[(long long)(m0 + tr * 4 + i) * Nn + n0 + tc * 4 + j] = acc[i][j] + bv;
    }
}

// ---------------- feature map: t=(relu(x)+eps)^2 ; t /= max(||t||2, 1e-12). In place on q,k ----------------
__global__ void featmap_kernel(float* __restrict__ qkv)
{
    int b = blockIdx.z;
    float* ptr = qkv + ((size_t)b * 768 + (blockIdx.y ? 256 : 0)) * NPOS;
    int tx = threadIdx.x, ty = threadIdx.y;          // 32 x 8
    int n = blockIdx.x * 32 + tx;
    float t[32];
    float s = 0.f;
#pragma unroll
    for (int r = 0; r < 32; ++r) {
        float v = ptr[(size_t)(ty * 32 + r) * NPOS + n];
        v = fmaxf(v, 0.f) + 1e-5f;
        v = v * v;
        t[r] = v;
        s += v * v;
    }
    __shared__ float red[8][33];
    __shared__ float nrm[32];
    red[ty][tx] = s;
    __syncthreads();
    if (ty == 0) {
        float tot = 0.f;
#pragma unroll
        for (int k = 0; k < 8; ++k) tot += red[k][tx];
        nrm[tx] = 1.f / fmaxf(sqrtf(tot), 1e-12f);
    }
    __syncthreads();
    float inv = nrm[tx];
#pragma unroll
    for (int r = 0; r < 32; ++r)
        ptr[(size_t)(ty * 32 + r) * NPOS + n] = t[r] * inv;
}

// ---------------- kmean[b,d] = mean_n k[b,d,n] ----------------
__global__ void kmean_kernel(const float* __restrict__ qkv, float* __restrict__ kmean)
{
    int d = blockIdx.x, b = blockIdx.y;
    const float* kp = qkv + ((size_t)b * 768 + 256 + d) * NPOS;
    float s = 0.f;
    for (int i = threadIdx.x; i < NPOS; i += 256) s += kp[i];
    __shared__ float red[256];
    red[threadIdx.x] = s;
    __syncthreads();
    for (int st = 128; st > 0; st >>= 1) {
        if (threadIdx.x < st) red[threadIdx.x] += red[threadIdx.x + st];
        __syncthreads();
    }
    if (threadIdx.x == 0) kmean[b * DIM + d] = red[0] * (1.f / (float)NPOS);
}

// ---------------- vkT[b,i,j] = (1/N) sum_n v[b,i,n] * k[b,j,n] ----------------
__global__ void vkt_kernel(const float* __restrict__ qkv, float* __restrict__ vkT)
{
    int b = blockIdx.z;
    const float* Vb = qkv + ((size_t)b * 768 + 512) * NPOS;
    const float* Kb = qkv + ((size_t)b * 768 + 256) * NPOS;
    int i0 = blockIdx.y * 64, j0 = blockIdx.x * 64;
    __shared__ float As[16][65], Bs[16][65];
    int tid = threadIdx.x, tr = tid >> 4, tc = tid & 15;
    float acc[4][4] = {};
    for (int k0 = 0; k0 < NPOS; k0 += 16) {
        for (int idx = tid; idx < 1024; idx += 256) {
            int r = idx >> 4, c = idx & 15;
            As[c][r] = Vb[(size_t)(i0 + r) * NPOS + k0 + c];
            Bs[c][r] = Kb[(size_t)(j0 + r) * NPOS + k0 + c];
        }
        __syncthreads();
#pragma unroll
        for (int kk = 0; kk < 16; ++kk) {
            float a[4], bb[4];
#pragma unroll
            for (int i = 0; i < 4; ++i) a[i] = As[kk][tr * 4 + i];
#pragma unroll
            for (int j = 0; j < 4; ++j) bb[j] = Bs[kk][tc * 4 + j];
#pragma unroll
            for (int i = 0; i < 4; ++i)
#pragma unroll
                for (int j = 0; j < 4; ++j) acc[i][j] += a[i] * bb[j];
        }
        __syncthreads();
    }
    const float sc = 1.f / (float)NPOS;
#pragma unroll
    for (int i = 0; i < 4; ++i)
#pragma unroll
        for (int j = 0; j < 4; ++j)
            vkT[((size_t)b * DIM + i0 + tr * 4 + i) * DIM + j0 + tc * 4 + j] = acc[i][j] * sc;
}

// ---------------- depthwise 5x5 SAME conv on v -> g_y ----------------
__global__ void dwconv_kernel(const float* __restrict__ qkv, const float* __restrict__ w,
                              const float* __restrict__ bias, float* __restrict__ y)
{
    int ch = blockIdx.x, b = blockIdx.y;
    const float* vp = qkv + ((size_t)b * 768 + 512 + ch) * NPOS;
    __shared__ float sm[68][68];
    __shared__ float ws[25];
    int tid = threadIdx.x;
    if (tid < 25) ws[tid] = w[ch * 25 + tid];
    for (int idx = tid; idx < 68 * 68; idx += 256) {
        int r = idx / 68, c = idx % 68;
        int gr = r - 2, gc = c - 2;
        sm[r][c] = (gr >= 0 && gr < HH && gc >= 0 && gc < WW) ? vp[gr * WW + gc] : 0.f;
    }
    __syncthreads();
    float bv = bias[ch];
    for (int p = tid; p < NPOS; p += 256) {
        int py = p >> 6, px = p & 63;
        float acc = bv;
#pragma unroll
        for (int ky = 0; ky < 5; ++ky)
#pragma unroll
            for (int kx = 0; kx < 5; ++kx)
                acc += sm[py + ky][px + kx] * ws[ky * 5 + kx];
        y[((size_t)b * DIM + ch) * NPOS + p] = acc;
    }
}

// ---------------- attn: (vkT @ q) / z, RMSNorm*norm_w, accumulate into g_y ----------------
__global__ void attn_kernel(const float* __restrict__ qkv, const float* __restrict__ vkT,
                            const float* __restrict__ kmean, const float* __restrict__ norm_w,
                            float* __restrict__ y)
{
    int b = blockIdx.y;
    int n0 = blockIdx.x * 32;
    int tx = threadIdx.x, ty = threadIdx.y;      // 32 x 8
    int tid = ty * 32 + tx;
    int n = n0 + tx;
    const float* qp = qkv + (size_t)b * 768 * NPOS;   // feature-mapped q
    const float* km = kmean + b * DIM;
    const float* vk = vkT + (size_t)b * DIM * DIM;

    __shared__ float red[8][33];
    __shared__ float zs[32];
    __shared__ float nw[256];
    __shared__ float vs[256][33];
    __shared__ float qs[32][33];

    nw[tid] = norm_w[tid];

    // z[n] = sum_j kmean[j] * q[j][n] + eps
    float zp = 0.f;
#pragma unroll
    for (int jj = 0; jj < 32; ++jj) {
        int j = ty * 32 + jj;
        zp += km[j] * qp[(size_t)j * NPOS + n];
    }
    red[ty][tx] = zp;
    __syncthreads();
    if (ty == 0) {
        float t = 0.f;
#pragma unroll
        for (int k = 0; k < 8; ++k) t += red[k][tx];
        zs[tx] = t + 1e-5f;
    }
    __syncthreads();

    // attn = vkT @ q  (each thread: 32 rows i = ty*32+r, one column n)
    float acc[32] = {};
    for (int jc = 0; jc < DIM; jc += 32) {
        for (int idx = tid; idx < 256 * 32; idx += 256) {
            int i = idx >> 5, j = idx & 31;
            vs[i][j] = vk[i * DIM + jc + j];
        }
        for (int idx = tid; idx < 32 * 32; idx += 256) {
            int j = idx >> 5, nn = idx & 31;
            qs[j][nn] = qp[(size_t)(jc + j) * NPOS + n0 + nn];
        }
        __syncthreads();
#pragma unroll
        for (int j = 0; j < 32; ++j) {
            float qv = qs[j][tx];
#pragma unroll
            for (int r = 0; r < 32; ++r)
                acc[r] += vs[ty * 32 + r][j] * qv;
        }
        __syncthreads();
    }

    // divide by z, RMS over channels
    float inv_z = 1.f / zs[tx];
    float ss = 0.f;
#pragma unroll
    for (int r = 0; r < 32; ++r) {
        acc[r] *= inv_z;
        ss += acc[r] * acc[r];
    }
    red[ty][tx] = ss;
    __syncthreads();
    if (ty == 0) {
        float t = 0.f;
#pragma unroll
        for (int k = 0; k < 8; ++k) t += red[k][tx];
        zs[tx] = rsqrtf(t * (1.f / (float)DIM) + 1e-5f);
    }
    __syncthreads();
    float rinv = zs[tx];
    float* yp = y + (size_t)b * DIM * NPOS;
#pragma unroll
    for (int r = 0; r < 32; ++r) {
        int i = ty * 32 + r;
        size_t off = (size_t)i * NPOS + n;
        yp[off] += acc[r] * rinv * nw[i];
    }
}

// ---------------- host ----------------
extern "C" void kernel_launch(void* const* d_in, const int* in_sizes, int n_in,
                              void* d_out, int out_size)
{
    const float* x      = (const float*)d_in[0];
    const float* qkv_w  = (const float*)d_in[1];
    const float* qkv_b  = (const float*)d_in[2];
    const float* dwc_w  = (const float*)d_in[3];
    const float* dwc_b  = (const float*)d_in[4];
    const float* norm_w = (const float*)d_in[5];
    const float* proj_w = (const float*)d_in[6];
    const float* proj_b = (const float*)d_in[7];
    float* out = (float*)d_out;

    float *p_qkv, *p_y, *p_vkT, *p_km;
    cudaGetSymbolAddress((void**)&p_qkv, g_qkv);
    cudaGetSymbolAddress((void**)&p_y, g_y);
    cudaGetSymbolAddress((void**)&p_vkT, g_vkT);
    cudaGetSymbolAddress((void**)&p_km, g_kmean);

    // 1. qkv = qkv_w @ x + qkv_b      [768,256]x[256,4096] per batch
    gemm64_kernel<<<dim3(NPOS / 64, 768 / 64, BATCH), 256>>>(
        qkv_w, x, qkv_b, p_qkv, 256, NPOS, (long long)DIM * NPOS, (long long)768 * NPOS);
    // 2. feature map on q and k (in place)
    featmap_kernel<<<dim3(NPOS / 32, 2, BATCH), dim3(32, 8)>>>(p_qkv);
    // 3. kmean
    kmean_kernel<<<dim3(DIM, BATCH), 256>>>(p_qkv, p_km);
    // 4. vkT
    vkt_kernel<<<dim3(DIM / 64, DIM / 64, BATCH), 256>>>(p_qkv, p_vkT);
    // 5. depthwise conv -> y
    dwconv_kernel<<<dim3(DIM, BATCH), 256>>>(p_qkv, dwc_w, dwc_b, p_y);
    // 6. attention path accumulates into y
    attn_kernel<<<dim3(NPOS / 32, BATCH), dim3(32, 8)>>>(p_qkv, p_vkT, p_km, norm_w, p_y);
    // 7. out = proj_w @ y + proj_b
    gemm64_kernel<<<dim3(NPOS / 64, DIM / 64, BATCH), 256>>>(
        proj_w, p_y, proj_b, out, 256, NPOS, (long long)DIM * NPOS, (long long)DIM * NPOS);
}

// round 3
// speedup vs baseline: 2.5434x; 2.5434x over previous
#include <cuda_runtime.h>
#include <cstdint>

#define BATCH 16
#define DIM   256
#define NPOS  4096   // 64*64
#define HH    64
#define WW    64
#define EPSF  1e-5f

// ---------------- scratch (no allocation allowed) ----------------
__device__ float g_qkv[(size_t)BATCH * 768 * NPOS];   // q rows 0-255, k 256-511, v 512-767
__device__ float g_y[(size_t)BATCH * DIM * NPOS];     // dw + normalized attn
__device__ float g_attn[(size_t)BATCH * DIM * NPOS];  // raw vkT@q
__device__ float g_vkT[(size_t)BATCH * DIM * DIM];
__device__ float g_part[(size_t)BATCH * 8 * DIM * DIM];
__device__ float g_kmean[BATCH * DIM];

// ---------------- packed f32x2 helpers (FFMA2 path: 2x fp32 rate on sm_103a) ----------------
__device__ __forceinline__ unsigned long long splat2(float v) {
    unsigned long long r; unsigned u = __float_as_uint(v);
    asm("mov.b64 %0, {%1, %1};" : "=l"(r) : "r"(u));
    return r;
}
__device__ __forceinline__ void fma2(unsigned long long& acc, unsigned long long a, unsigned long long b) {
    asm("fma.rn.f32x2 %0, %1, %2, %0;" : "+l"(acc) : "l"(a), "l"(b));
}
__device__ __forceinline__ float2 unpack2(unsigned long long p) {
    unsigned lo, hi;
    asm("mov.b64 {%0, %1}, %2;" : "=r"(lo), "=r"(hi) : "l"(p));
    return make_float2(__uint_as_float(lo), __uint_as_float(hi));
}

// ---------------- 128x128-tile SGEMM (FFMA2): C[b] = A[b][M,K] * X[b][K,Nn] + bias ----------------
// A row-major [M,K]; X row-major [K,Nn]; 256 threads, 8x8 outputs/thread (2x2 of 4x4 subtiles).
__global__ __launch_bounds__(256, 2)
void sgemm128_kernel(const float* __restrict__ A, const float* __restrict__ X,
                     const float* __restrict__ bias, float* __restrict__ C,
                     int K, int Nn, long long aStrideB, long long xStrideB, long long cStrideB)
{
    int b = blockIdx.z;
    const float* Ab = A + (long long)b * aStrideB;
    const float* Xb = X + (long long)b * xStrideB;
    float* Cb = C + (long long)b * cStrideB;
    int m0 = blockIdx.y * 128, n0 = blockIdx.x * 128;
    __shared__ float As[16][132];   // As[k][m]
    __shared__ float Bs[16][132];   // Bs[k][n]
    int tid = threadIdx.x;
    int tr = tid >> 4, tc = tid & 15;

    unsigned long long acc[8][4];
#pragma unroll
    for (int i = 0; i < 8; ++i) {
        int row = m0 + (i < 4 ? tr * 4 + i : 64 + tr * 4 + (i - 4));
        unsigned long long bv = splat2(bias ? bias[row] : 0.f);
#pragma unroll
        for (int j = 0; j < 4; ++j) acc[i][j] = bv;
    }

    for (int k0 = 0; k0 < K; k0 += 16) {
#pragma unroll
        for (int l = 0; l < 2; ++l) {
            int idx = tid + l * 256;
            int r = idx >> 2, c4 = (idx & 3) * 4;
            float4 v = *(const float4*)&Ab[(size_t)(m0 + r) * K + k0 + c4];
            As[c4 + 0][r] = v.x; As[c4 + 1][r] = v.y; As[c4 + 2][r] = v.z; As[c4 + 3][r] = v.w;
        }
#pragma unroll
        for (int l = 0; l < 2; ++l) {
            int idx = tid + l * 256;
            int r = idx >> 5, c = (idx & 31) * 4;
            *(float4*)&Bs[r][c] = *(const float4*)&Xb[(size_t)(k0 + r) * Nn + n0 + c];
        }
        __syncthreads();
#pragma unroll
        for (int kk = 0; kk < 16; ++kk) {
            float4 a0 = *(const float4*)&As[kk][tr * 4];
            float4 a1 = *(const float4*)&As[kk][64 + tr * 4];
            ulonglong2 b0 = *(const ulonglong2*)&Bs[kk][tc * 4];
            ulonglong2 b1 = *(const ulonglong2*)&Bs[kk][64 + tc * 4];
            unsigned long long bp0 = b0.x, bp1 = b0.y, bp2 = b1.x, bp3 = b1.y;
            float av[8] = {a0.x, a0.y, a0.z, a0.w, a1.x, a1.y, a1.z, a1.w};
#pragma unroll
            for (int i = 0; i < 8; ++i) {
                unsigned long long a2 = splat2(av[i]);
                fma2(acc[i][0], a2, bp0);
                fma2(acc[i][1], a2, bp1);
                fma2(acc[i][2], a2, bp2);
                fma2(acc[i][3], a2, bp3);
            }
        }
        __syncthreads();
    }

#pragma unroll
    for (int i = 0; i < 8; ++i) {
        int row = m0 + (i < 4 ? tr * 4 + i : 64 + tr * 4 + (i - 4));
        float2 c0 = unpack2(acc[i][0]), c1 = unpack2(acc[i][1]);
        *(float4*)&Cb[(size_t)row * Nn + n0 + tc * 4] = make_float4(c0.x, c0.y, c1.x, c1.y);
        float2 c2 = unpack2(acc[i][2]), c3 = unpack2(acc[i][3]);
        *(float4*)&Cb[(size_t)row * Nn + n0 + 64 + tc * 4] = make_float4(c2.x, c2.y, c3.x, c3.y);
    }
}

// ---------------- vkT split-K partials: part[z] = V_tile * K_tile^T over k-chunk of 512 ----------------
__global__ __launch_bounds__(256, 2)
void vkt128_kernel(const float* __restrict__ qkv, float* __restrict__ part)
{
    int z = blockIdx.z;
    int b = z >> 3, ck = z & 7;
    const float* Vb = qkv + ((size_t)b * 768 + 512) * NPOS;
    const float* Kb = qkv + ((size_t)b * 768 + 256) * NPOS;
    int i0 = blockIdx.y * 128, j0 = blockIdx.x * 128;
    int kbase = ck * 512;
    __shared__ float As[16][132];   // As[k][i] from V
    __shared__ float Bs[16][132];   // Bs[k][j] from K
    int tid = threadIdx.x;
    int tr = tid >> 4, tc = tid & 15;
    unsigned long long acc[8][4] = {};

    for (int k0 = 0; k0 < 512; k0 += 16) {
#pragma unroll
        for (int l = 0; l < 2; ++l) {
            int idx = tid + l * 256;
            int r = idx >> 2, c4 = (idx & 3) * 4;
            float4 v = *(const float4*)&Vb[(size_t)(i0 + r) * NPOS + kbase + k0 + c4];
            As[c4 + 0][r] = v.x; As[c4 + 1][r] = v.y; As[c4 + 2][r] = v.z; As[c4 + 3][r] = v.w;
            float4 w = *(const float4*)&Kb[(size_t)(j0 + r) * NPOS + kbase + k0 + c4];
            Bs[c4 + 0][r] = w.x; Bs[c4 + 1][r] = w.y; Bs[c4 + 2][r] = w.z; Bs[c4 + 3][r] = w.w;
        }
        __syncthreads();
#pragma unroll
        for (int kk = 0; kk < 16; ++kk) {
            float4 a0 = *(const float4*)&As[kk][tr * 4];
            float4 a1 = *(const float4*)&As[kk][64 + tr * 4];
            ulonglong2 b0 = *(const ulonglong2*)&Bs[kk][tc * 4];
            ulonglong2 b1 = *(const ulonglong2*)&Bs[kk][64 + tc * 4];
            unsigned long long bp0 = b0.x, bp1 = b0.y, bp2 = b1.x, bp3 = b1.y;
            float av[8] = {a0.x, a0.y, a0.z, a0.w, a1.x, a1.y, a1.z, a1.w};
#pragma unroll
            for (int i = 0; i < 8; ++i) {
                unsigned long long a2 = splat2(av[i]);
                fma2(acc[i][0], a2, bp0);
                fma2(acc[i][1], a2, bp1);
                fma2(acc[i][2], a2, bp2);
                fma2(acc[i][3], a2, bp3);
            }
        }
        __syncthreads();
    }

    float* P = part + (size_t)z * DIM * DIM;
#pragma unroll
    for (int i = 0; i < 8; ++i) {
        int row = i0 + (i < 4 ? tr * 4 + i : 64 + tr * 4 + (i - 4));
        float2 c0 = unpack2(acc[i][0]), c1 = unpack2(acc[i][1]);
        *(float4*)&P[(size_t)row * DIM + j0 + tc * 4] = make_float4(c0.x, c0.y, c1.x, c1.y);
        float2 c2 = unpack2(acc[i][2]), c3 = unpack2(acc[i][3]);
        *(float4*)&P[(size_t)row * DIM + j0 + 64 + tc * 4] = make_float4(c2.x, c2.y, c3.x, c3.y);
    }
}

__global__ void vkt_reduce_kernel(const float* __restrict__ part, float* __restrict__ vkT)
{
    int idx = blockIdx.x * 256 + threadIdx.x;    // [0, 16*65536)
    int b = idx >> 16, ij = idx & 65535;
    float s = 0.f;
#pragma unroll
    for (int c = 0; c < 8; ++c) s += part[(size_t)(b * 8 + c) * 65536 + ij];
    vkT[idx] = s * (1.f / (float)NPOS);
}

// ---------------- feature map: t=(relu(x)+eps)^2 ; t /= max(||t||2, 1e-12). In place on q,k ----------------
__global__ void featmap_kernel(float* __restrict__ qkv)
{
    int b = blockIdx.z;
    float* ptr = qkv + ((size_t)b * 768 + (blockIdx.y ? 256 : 0)) * NPOS;
    int tx = threadIdx.x, ty = threadIdx.y;          // 32 x 8
    int n = blockIdx.x * 32 + tx;
    float t[32];
    float s = 0.f;
#pragma unroll
    for (int r = 0; r < 32; ++r) {
        float v = ptr[(size_t)(ty * 32 + r) * NPOS + n];
        v = fmaxf(v, 0.f) + EPSF;
        v = v * v;
        t[r] = v;
        s += v * v;
    }
    __shared__ float red[8][33];
    __shared__ float nrm[32];
    red[ty][tx] = s;
    __syncthreads();
    if (ty == 0) {
        float tot = 0.f;
#pragma unroll
        for (int k = 0; k < 8; ++k) tot += red[k][tx];
        nrm[tx] = 1.f / fmaxf(sqrtf(tot), 1e-12f);
    }
    __syncthreads();
    float inv = nrm[tx];
#pragma unroll
    for (int r = 0; r < 32; ++r)
        ptr[(size_t)(ty * 32 + r) * NPOS + n] = t[r] * inv;
}

// ---------------- kmean[b,d] = mean_n k[b,d,n] ----------------
__global__ void kmean_kernel(const float* __restrict__ qkv, float* __restrict__ kmean)
{
    int d = blockIdx.x, b = blockIdx.y;
    const float* kp = qkv + ((size_t)b * 768 + 256 + d) * NPOS;
    float s = 0.f;
    for (int i = threadIdx.x; i < NPOS; i += 256) s += kp[i];
    __shared__ float red[256];
    red[threadIdx.x] = s;
    __syncthreads();
    for (int st = 128; st > 0; st >>= 1) {
        if (threadIdx.x < st) red[threadIdx.x] += red[threadIdx.x + st];
        __syncthreads();
    }
    if (threadIdx.x == 0) kmean[b * DIM + d] = red[0] * (1.f / (float)NPOS);
}

// ---------------- depthwise 5x5 SAME conv on v -> g_y ----------------
__global__ void dwconv_kernel(const float* __restrict__ qkv, const float* __restrict__ w,
                              const float* __restrict__ bias, float* __restrict__ y)
{
    int ch = blockIdx.x, b = blockIdx.y;
    const float* vp = qkv + ((size_t)b * 768 + 512 + ch) * NPOS;
    __shared__ float sm[68][68];
    __shared__ float ws[25];
    int tid = threadIdx.x;
    if (tid < 25) ws[tid] = w[ch * 25 + tid];
    for (int idx = tid; idx < 68 * 68; idx += 256) {
        int r = idx / 68, c = idx % 68;
        int gr = r - 2, gc = c - 2;
        sm[r][c] = (gr >= 0 && gr < HH && gc >= 0 && gc < WW) ? vp[gr * WW + gc] : 0.f;
    }
    __syncthreads();
    float bv = bias[ch];
    for (int p = tid; p < NPOS; p += 256) {
        int py = p >> 6, px = p & 63;
        float acc = bv;
#pragma unroll
        for (int ky = 0; ky < 5; ++ky)
#pragma unroll
            for (int kx = 0; kx < 5; ++kx)
                acc += sm[py + ky][px + kx] * ws[ky * 5 + kx];
        y[((size_t)b * DIM + ch) * NPOS + p] = acc;
    }
}

// ---------------- fused: z-GEMV + /z + RMSNorm*norm_w, accumulate into y ----------------
__global__ void attn_norm_kernel(const float* __restrict__ qkv, const float* __restrict__ attn,
                                 const float* __restrict__ kmean, const float* __restrict__ norm_w,
                                 float* __restrict__ y)
{
    int b = blockIdx.y;
    int tx = threadIdx.x, ty = threadIdx.y;  // 32 x 8
    int tid = ty * 32 + tx;
    int n = blockIdx.x * 32 + tx;
    const float* qp = qkv + (size_t)b * 768 * NPOS;
    const float* ap = attn + (size_t)b * DIM * NPOS;
    __shared__ float km[256], nw[256];
    __shared__ float red[8][33];
    __shared__ float zz[32];
    km[tid] = kmean[b * DIM + tid];
    nw[tid] = norm_w[tid];
    __syncthreads();

    float t[32];
    float zp = 0.f;
#pragma unroll
    for (int r = 0; r < 32; ++r) {
        int i = ty * 32 + r;
        zp += km[i] * qp[(size_t)i * NPOS + n];
        t[r] = ap[(size_t)i * NPOS + n];
    }
    red[ty][tx] = zp;
    __syncthreads();
    if (ty == 0) {
        float s = 0.f;
#pragma unroll
        for (int k = 0; k < 8; ++k) s += red[k][tx];
        zz[tx] = 1.f / (s + EPSF);
    }
    __syncthreads();
    float invz = zz[tx];
    float ss = 0.f;
#pragma unroll
    for (int r = 0; r < 32; ++r) { t[r] *= invz; ss += t[r] * t[r]; }
    __syncthreads();
    red[ty][tx] = ss;
    __syncthreads();
    if (ty == 0) {
        float s = 0.f;
#pragma unroll
        for (int k = 0; k < 8; ++k) s += red[k][tx];
        zz[tx] = rsqrtf(s * (1.f / (float)DIM) + EPSF);
    }
    __syncthreads();
    float rinv = zz[tx];
    float* yp = y + (size_t)b * DIM * NPOS;
#pragma unroll
    for (int r = 0; r < 32; ++r) {
        int i = ty * 32 + r;
        yp[(size_t)i * NPOS + n] += t[r] * rinv * nw[i];
    }
}

// ---------------- host ----------------
extern "C" void kernel_launch(void* const* d_in, const int* in_sizes, int n_in,
                              void* d_out, int out_size)
{
    const float* x      = (const float*)d_in[0];
    const float* qkv_w  = (const float*)d_in[1];
    const float* qkv_b  = (const float*)d_in[2];
    const float* dwc_w  = (const float*)d_in[3];
    const float* dwc_b  = (const float*)d_in[4];
    const float* norm_w = (const float*)d_in[5];
    const float* proj_w = (const float*)d_in[6];
    const float* proj_b = (const float*)d_in[7];
    float* out = (float*)d_out;

    float *p_qkv, *p_y, *p_attn, *p_vkT, *p_part, *p_km;
    cudaGetSymbolAddress((void**)&p_qkv, g_qkv);
    cudaGetSymbolAddress((void**)&p_y, g_y);
    cudaGetSymbolAddress((void**)&p_attn, g_attn);
    cudaGetSymbolAddress((void**)&p_vkT, g_vkT);
    cudaGetSymbolAddress((void**)&p_part, g_part);
    cudaGetSymbolAddress((void**)&p_km, g_kmean);

    // 1. qkv = qkv_w @ x + qkv_b      [768,256]x[256,4096] per batch
    sgemm128_kernel<<<dim3(NPOS / 128, 768 / 128, BATCH), 256>>>(
        qkv_w, x, qkv_b, p_qkv, 256, NPOS,
        0LL, (long long)DIM * NPOS, (long long)768 * NPOS);
    // 2. feature map on q and k (in place)
    featmap_kernel<<<dim3(NPOS / 32, 2, BATCH), dim3(32, 8)>>>(p_qkv);
    // 3. kmean
    kmean_kernel<<<dim3(DIM, BATCH), 256>>>(p_qkv, p_km);
    // 4. vkT split-K partials + reduce
    vkt128_kernel<<<dim3(2, 2, BATCH * 8), 256>>>(p_qkv, p_part);
    vkt_reduce_kernel<<<dim3(BATCH * DIM * DIM / 256), 256>>>(p_part, p_vkT);
    // 5. depthwise conv -> y
    dwconv_kernel<<<dim3(DIM, BATCH), 256>>>(p_qkv, dwc_w, dwc_b, p_y);
    // 6. attn_raw = vkT @ q
    sgemm128_kernel<<<dim3(NPOS / 128, DIM / 128, BATCH), 256>>>(
        p_vkT, p_qkv, nullptr, p_attn, DIM, NPOS,
        (long long)DIM * DIM, (long long)768 * NPOS, (long long)DIM * NPOS);
    // 7. z + /z + RMSNorm, accumulate into y
    attn_norm_kernel<<<dim3(NPOS / 32, BATCH), dim3(32, 8)>>>(p_qkv, p_attn, p_km, norm_w, p_y);
    // 8. out = proj_w @ y + proj_b
    sgemm128_kernel<<<dim3(NPOS / 128, DIM / 128, BATCH), 256>>>(
        proj_w, p_y, proj_b, out, 256, NPOS,
        0LL, (long long)DIM * NPOS, (long long)DIM * NPOS);
}

// round 6
// speedup vs baseline: 2.6613x; 1.0464x over previous
#include <cuda_runtime.h>
#include <cstdint>

#define BATCH 16
#define DIM   256
#define NPOS  4096
#define QKVD  768
#define HH    64
#define WW    64
#define EPSF  1e-5f

// ---------------- scratch ----------------
__device__ float g_xt [(size_t)BATCH * NPOS * DIM];    // x transposed [b][n][c]
__device__ float g_qkv[(size_t)BATCH * NPOS * QKVD];   // [b][n][768] q 0-255, k 256-511, v 512-767
__device__ float g_kdn[(size_t)BATCH * DIM * NPOS];    // featmapped k [b][d][n]
__device__ float g_vdn[(size_t)BATCH * DIM * NPOS];    // v [b][d][n]
__device__ float g_vkT[(size_t)BATCH * DIM * DIM];
__device__ float g_part[(size_t)BATCH * 4 * DIM * DIM];
__device__ float g_attn[(size_t)BATCH * DIM * NPOS];   // [b][d][n]
__device__ float g_dw [(size_t)BATCH * DIM * NPOS];    // [b][d][n]
__device__ float g_y  [(size_t)BATCH * NPOS * DIM];    // [b][n][d]
__device__ float g_z  [(size_t)BATCH * NPOS];
__device__ float g_kmean[BATCH * DIM];

__device__ __forceinline__ uint32_t f2tf32(float v) {
    uint32_t u;
    asm("cvt.rn.tf32.f32 %0, %1;" : "=r"(u) : "f"(v));
    return u;
}

// ---------------- tf32 mma.sync GEMM: D[128m x 128n] = A[m,K]·B[n,K]^T (+bias) ----------------
// A,B row-major K-contiguous. grid (Ntiles, Mtiles, batch*kChunks). 256 threads.
// biasMode: 0 none, 1 per-col (n), 2 per-row (m)
__global__ __launch_bounds__(256)
void mma_gemm(const float* __restrict__ A, const float* __restrict__ B,
              const float* __restrict__ bias, float* __restrict__ C,
              int K, int ldA, int ldB, int ldC,
              long long aStride, long long bStride, long long cStride,
              int kChunks, int biasMode)
{
    __shared__ uint32_t As[2][16][132];
    __shared__ uint32_t Bs[2][16][132];

    int z = blockIdx.z;
    int b = z / kChunks, chunk = z - b * kChunks;
    int m0 = blockIdx.y * 128, n0 = blockIdx.x * 128;
    const float* Ab = A + (size_t)b * aStride + (size_t)m0 * ldA + (size_t)chunk * K;
    const float* Bb = B + (size_t)b * bStride + (size_t)n0 * ldB + (size_t)chunk * K;
    float* Cb = C + (size_t)z * cStride;

    int tid = threadIdx.x;
    int lane = tid & 31, wid = tid >> 5;
    int g = lane >> 2, tig = lane & 3;
    int warp_m = (wid & 1) * 64, warp_n = (wid >> 1) * 32;

    int lr = tid & 127;            // tile row this thread loads
    int lc = (tid >> 7) * 8;       // col base: 0 or 8

    float acc[4][4][4];
#pragma unroll
    for (int i = 0; i < 4; ++i)
#pragma unroll
        for (int j = 0; j < 4; ++j)
#pragma unroll
            for (int r = 0; r < 4; ++r) acc[i][j][r] = 0.f;

    int S = K >> 4;
    float4 pa0, pa1, pb0, pb1;
    const float* ar = Ab + (size_t)lr * ldA + lc;
    const float* br = Bb + (size_t)lr * ldB + lc;

    // stage 0 load + store
    pa0 = *(const float4*)(ar);
    pa1 = *(const float4*)(ar + 4);
    pb0 = *(const float4*)(br);
    pb1 = *(const float4*)(br + 4);
    {
        As[0][lc + 0][lr] = f2tf32(pa0.x); As[0][lc + 1][lr] = f2tf32(pa0.y);
        As[0][lc + 2][lr] = f2tf32(pa0.z); As[0][lc + 3][lr] = f2tf32(pa0.w);
        As[0][lc + 4][lr] = f2tf32(pa1.x); As[0][lc + 5][lr] = f2tf32(pa1.y);
        As[0][lc + 6][lr] = f2tf32(pa1.z); As[0][lc + 7][lr] = f2tf32(pa1.w);
        Bs[0][lc + 0][lr] = f2tf32(pb0.x); Bs[0][lc + 1][lr] = f2tf32(pb0.y);
        Bs[0][lc + 2][lr] = f2tf32(pb0.z); Bs[0][lc + 3][lr] = f2tf32(pb0.w);
        Bs[0][lc + 4][lr] = f2tf32(pb1.x); Bs[0][lc + 5][lr] = f2tf32(pb1.y);
        Bs[0][lc + 6][lr] = f2tf32(pb1.z); Bs[0][lc + 7][lr] = f2tf32(pb1.w);
    }
    __syncthreads();

    for (int s = 0; s < S; ++s) {
        if (s + 1 < S) {
            int kc = (s + 1) * 16;
            pa0 = *(const float4*)(ar + kc);
            pa1 = *(const float4*)(ar + kc + 4);
            pb0 = *(const float4*)(br + kc);
            pb1 = *(const float4*)(br + kc + 4);
        }
        int buf = s & 1;
#pragma unroll
        for (int kb = 0; kb < 16; kb += 8) {
            uint32_t af[4][4], bf[4][2];
#pragma unroll
            for (int i = 0; i < 4; ++i) {
                int r0 = warp_m + i * 16 + g;
                af[i][0] = As[buf][kb + tig][r0];
                af[i][1] = As[buf][kb + tig][r0 + 8];
                af[i][2] = As[buf][kb + tig + 4][r0];
                af[i][3] = As[buf][kb + tig + 4][r0 + 8];
            }
#pragma unroll
            for (int j = 0; j < 4; ++j) {
                int c0 = warp_n + j * 8 + g;
                bf[j][0] = Bs[buf][kb + tig][c0];
                bf[j][1] = Bs[buf][kb + tig + 4][c0];
            }
#pragma unroll
            for (int i = 0; i < 4; ++i)
#pragma unroll
                for (int j = 0; j < 4; ++j)
                    asm volatile(
                        "mma.sync.aligned.m16n8k8.row.col.f32.tf32.tf32.f32 "
                        "{%0,%1,%2,%3}, {%4,%5,%6,%7}, {%8,%9}, {%0,%1,%2,%3};"
                        : "+f"(acc[i][j][0]), "+f"(acc[i][j][1]),
                          "+f"(acc[i][j][2]), "+f"(acc[i][j][3])
                        : "r"(af[i][0]), "r"(af[i][1]), "r"(af[i][2]), "r"(af[i][3]),
                          "r"(bf[j][0]), "r"(bf[j][1]));
        }
        if (s + 1 < S) {
            int nb = (s + 1) & 1;
            As[nb][lc + 0][lr] = f2tf32(pa0.x); As[nb][lc + 1][lr] = f2tf32(pa0.y);
            As[nb][lc + 2][lr] = f2tf32(pa0.z); As[nb][lc + 3][lr] = f2tf32(pa0.w);
            As[nb][lc + 4][lr] = f2tf32(pa1.x); As[nb][lc + 5][lr] = f2tf32(pa1.y);
            As[nb][lc + 6][lr] = f2tf32(pa1.z); As[nb][lc + 7][lr] = f2tf32(pa1.w);
            Bs[nb][lc + 0][lr] = f2tf32(pb0.x); Bs[nb][lc + 1][lr] = f2tf32(pb0.y);
            Bs[nb][lc + 2][lr] = f2tf32(pb0.z); Bs[nb][lc + 3][lr] = f2tf32(pb0.w);
            Bs[nb][lc + 4][lr] = f2tf32(pb1.x); Bs[nb][lc + 5][lr] = f2tf32(pb1.y);
            Bs[nb][lc + 6][lr] = f2tf32(pb1.z); Bs[nb][lc + 7][lr] = f2tf32(pb1.w);
        }
        __syncthreads();
    }

    // epilogue
#pragma unroll
    for (int i = 0; i < 4; ++i) {
        int row0 = m0 + warp_m + i * 16 + g;
        float br0 = 0.f, br1 = 0.f;
        if (biasMode == 2) { br0 = bias[row0]; br1 = bias[row0 + 8]; }
#pragma unroll
        for (int j = 0; j < 4; ++j) {
            int col = n0 + warp_n + j * 8 + tig * 2;
            float bc0 = 0.f, bc1 = 0.f;
            if (biasMode == 1) { bc0 = bias[col]; bc1 = bias[col + 1]; }
            else if (biasMode == 2) { bc0 = br0; bc1 = br0; }
            float2 v0 = make_float2(acc[i][j][0] + bc0, acc[i][j][1] + bc1);
            if (biasMode == 2) { bc0 = br1; bc1 = br1; }
            float2 v1 = make_float2(acc[i][j][2] + bc0, acc[i][j][3] + bc1);
            *(float2*)&Cb[(size_t)row0 * ldC + col] = v0;
            *(float2*)&Cb[(size_t)(row0 + 8) * ldC + col] = v1;
        }
    }
}

// ---------------- transpose x [c,n] -> [n,c] ----------------
__global__ void transpose_x(const float* __restrict__ x, float* __restrict__ xt)
{
    __shared__ float t[32][33];
    int b = blockIdx.z;
    int n0 = blockIdx.x * 32, c0 = blockIdx.y * 32;
    const float* xb = x + (size_t)b * DIM * NPOS;
    float* xo = xt + (size_t)b * NPOS * DIM;
    int tx = threadIdx.x, ty = threadIdx.y;
#pragma unroll
    for (int j = 0; j < 4; ++j)
        t[ty + j * 8][tx] = xb[(size_t)(c0 + ty + j * 8) * NPOS + n0 + tx];
    __syncthreads();
#pragma unroll
    for (int j = 0; j < 4; ++j)
        xo[(size_t)(n0 + ty + j * 8) * DIM + c0 + tx] = t[tx][ty + j * 8];
}

// ---------------- featmap (q in-place; k featmap+transpose; v transpose) ----------------
__global__ void featmap_tr(float* __restrict__ qkv, float* __restrict__ kdn, float* __restrict__ vdn)
{
    __shared__ float t[32][257];
    int mode = blockIdx.y;             // 0=q, 1=k, 2=v
    int b = blockIdx.z;
    int n0 = blockIdx.x * 32;
    int tid = threadIdx.x, wid = tid >> 5, lid = tid & 31;
    float* base = qkv + (size_t)b * NPOS * QKVD + mode * 256;

#pragma unroll
    for (int rr = 0; rr < 4; ++rr) {
        int n = wid * 4 + rr;
        float* rp = base + (size_t)(n0 + n) * QKVD;
        float v[8];
        float ss = 0.f;
#pragma unroll
        for (int j = 0; j < 8; ++j) {
            float u = rp[lid + 32 * j];
            if (mode < 2) {
                u = fmaxf(u, 0.f) + EPSF;
                u = u * u;
                ss += u * u;
            }
            v[j] = u;
        }
        if (mode < 2) {
#pragma unroll
            for (int o = 16; o > 0; o >>= 1) ss += __shfl_xor_sync(0xFFFFFFFFu, ss, o);
            float inv = 1.f / fmaxf(sqrtf(ss), 1e-12f);
#pragma unroll
            for (int j = 0; j < 8; ++j) v[j] *= inv;
        }
        if (mode == 0) {
#pragma unroll
            for (int j = 0; j < 8; ++j) rp[lid + 32 * j] = v[j];
        } else {
#pragma unroll
            for (int j = 0; j < 8; ++j) t[n][lid + 32 * j] = v[j];
        }
    }
    if (mode == 0) return;
    __syncthreads();
    float* out = (mode == 1 ? kdn : vdn) + (size_t)b * DIM * NPOS;
    float* op = out + (size_t)tid * NPOS + n0;      // thread owns channel d = tid
#pragma unroll
    for (int nn = 0; nn < 32; nn += 4)
        *(float4*)&op[nn] = make_float4(t[nn][tid], t[nn + 1][tid], t[nn + 2][tid], t[nn + 3][tid]);
}

// ---------------- kmean over n of k_dn ----------------
__global__ void kmean_k(const float* __restrict__ kdn, float* __restrict__ km)
{
    int d = blockIdx.x, b = blockIdx.y;
    const float* kp = kdn + ((size_t)b * DIM + d) * NPOS;
    float s = 0.f;
    for (int i = threadIdx.x; i < NPOS; i += 256) s += kp[i];
    __shared__ float red[256];
    red[threadIdx.x] = s;
    __syncthreads();
    for (int st = 128; st > 0; st >>= 1) {
        if (threadIdx.x < st) red[threadIdx.x] += red[threadIdx.x + st];
        __syncthreads();
    }
    if (threadIdx.x == 0) km[b * DIM + d] = red[0] * (1.f / (float)NPOS);
}

// ---------------- z[b][n] = kmean · q_nd[n] + eps ----------------
__global__ void zcalc(const float* __restrict__ qkv, const float* __restrict__ km, float* __restrict__ zo)
{
    __shared__ float kms[256];
    int b = blockIdx.y;
    int tid = threadIdx.x, wid = tid >> 5, lid = tid & 31;
    kms[tid] = km[b * DIM + tid];
    __syncthreads();
    int n = blockIdx.x * 8 + wid;
    const float* qp = qkv + ((size_t)b * NPOS + n) * QKVD;
    float s = 0.f;
#pragma unroll
    for (int j = 0; j < 8; ++j) s += kms[lid + 32 * j] * qp[lid + 32 * j];
#pragma unroll
    for (int o = 16; o > 0; o >>= 1) s += __shfl_xor_sync(0xFFFFFFFFu, s, o);
    if (lid == 0) zo[(size_t)b * NPOS + n] = s + EPSF;
}

// ---------------- vkt reduce (4 split-K chunks) + 1/N scale ----------------
__global__ void vkt_reduce(const float* __restrict__ part, float* __restrict__ vkT)
{
    int idx = blockIdx.x * 256 + threadIdx.x;
    int b = idx >> 16, ij = idx & 65535;
    float s = 0.f;
#pragma unroll
    for (int c = 0; c < 4; ++c) s += part[(size_t)(b * 4 + c) * 65536 + ij];
    vkT[idx] = s * (1.f / (float)NPOS);
}

// ---------------- depthwise 5x5 on v_dn -> dw_dn ----------------
__global__ void dwconv_kernel(const float* __restrict__ vdn, const float* __restrict__ w,
                              const float* __restrict__ bias, float* __restrict__ dw)
{
    int ch = blockIdx.x, b = blockIdx.y;
    const float* vp = vdn + ((size_t)b * DIM + ch) * NPOS;
    __shared__ float sm[68][68];
    __shared__ float ws[25];
    int tid = threadIdx.x;
    if (tid < 25) ws[tid] = w[ch * 25 + tid];
    for (int idx = tid; idx < 68 * 68; idx += 256) {
        int r = idx / 68, c = idx % 68;
        int gr = r - 2, gc = c - 2;
        sm[r][c] = (gr >= 0 && gr < HH && gc >= 0 && gc < WW) ? vp[gr * WW + gc] : 0.f;
    }
    __syncthreads();
    float bv = bias[ch];
    for (int p = tid; p < NPOS; p += 256) {
        int py = p >> 6, px = p & 63;
        float acc = bv;
#pragma unroll
        for (int ky = 0; ky < 5; ++ky)
#pragma unroll
            for (int kx = 0; kx < 5; ++kx)
                acc += sm[py + ky][px + kx] * ws[ky * 5 + kx];
        dw[((size_t)b * DIM + ch) * NPOS + p] = acc;
    }
}

// ---------------- attn/z/RMS/norm_w + dw  ->  y_nd ----------------
__global__ void attn_norm(const float* __restrict__ attn, const float* __restrict__ dw,
                          const float* __restrict__ zbuf, const float* __restrict__ norm_w,
                          float* __restrict__ y)
{
    int b = blockIdx.y;
    int n0 = blockIdx.x * 32;
    int tx = threadIdx.x, ty = threadIdx.y;
    int tid = ty * 32 + tx;
    int n = n0 + tx;
    __shared__ float nw[256];
    __shared__ float red[8][33];
    __shared__ float rr[32];
    nw[tid] = norm_w[tid];
    __syncthreads();
    const float* ap = attn + (size_t)b * DIM * NPOS;
    const float* dp = dw + (size_t)b * DIM * NPOS;
    float invz = 1.f / zbuf[(size_t)b * NPOS + n];
    float t[32];
    float ss = 0.f;
#pragma unroll
    for (int r = 0; r < 32; ++r) {
        int i = ty * 32 + r;
        t[r] = ap[(size_t)i * NPOS + n] * invz;
        ss += t[r] * t[r];
    }
    red[ty][tx] = ss;
    __syncthreads();
    if (ty == 0) {
        float s = 0.f;
#pragma unroll
        for (int k = 0; k < 8; ++k) s += red[k][tx];
        rr[tx] = rsqrtf(s * (1.f / (float)DIM) + EPSF);
    }
    __syncthreads();
    float ri = rr[tx];
    float* yp = y + ((size_t)b * NPOS + n) * DIM + ty * 32;
#pragma unroll
    for (int r = 0; r < 32; r += 4) {
        float4 o;
        o.x = t[r + 0] * ri * nw[ty * 32 + r + 0] + dp[(size_t)(ty * 32 + r + 0) * NPOS + n];
        o.y = t[r + 1] * ri * nw[ty * 32 + r + 1] + dp[(size_t)(ty * 32 + r + 1) * NPOS + n];
        o.z = t[r + 2] * ri * nw[ty * 32 + r + 2] + dp[(size_t)(ty * 32 + r + 2) * NPOS + n];
        o.w = t[r + 3] * ri * nw[ty * 32 + r + 3] + dp[(size_t)(ty * 32 + r + 3) * NPOS + n];
        *(float4*)&yp[r] = o;
    }
}

// ---------------- host ----------------
extern "C" void kernel_launch(void* const* d_in, const int* in_sizes, int n_in,
                              void* d_out, int out_size)
{
    const float* x      = (const float*)d_in[0];
    const float* qkv_w  = (const float*)d_in[1];
    const float* qkv_b  = (const float*)d_in[2];
    const float* dwc_w  = (const float*)d_in[3];
    const float* dwc_b  = (const float*)d_in[4];
    const float* norm_w = (const float*)d_in[5];
    const float* proj_w = (const float*)d_in[6];
    const float* proj_b = (const float*)d_in[7];
    float* out = (float*)d_out;

    float *p_xt, *p_qkv, *p_kdn, *p_vdn, *p_vkT, *p_part, *p_attn, *p_dw, *p_y, *p_z, *p_km;
    cudaGetSymbolAddress((void**)&p_xt, g_xt);
    cudaGetSymbolAddress((void**)&p_qkv, g_qkv);
    cudaGetSymbolAddress((void**)&p_kdn, g_kdn);
    cudaGetSymbolAddress((void**)&p_vdn, g_vdn);
    cudaGetSymbolAddress((void**)&p_vkT, g_vkT);
    cudaGetSymbolAddress((void**)&p_part, g_part);
    cudaGetSymbolAddress((void**)&p_attn, g_attn);
    cudaGetSymbolAddress((void**)&p_dw, g_dw);
    cudaGetSymbolAddress((void**)&p_y, g_y);
    cudaGetSymbolAddress((void**)&p_z, g_z);
    cudaGetSymbolAddress((void**)&p_km, g_kmean);

    // 1. x [c,n] -> x_nd [n,c]
    transpose_x<<<dim3(NPOS / 32, DIM / 32, BATCH), dim3(32, 8)>>>(x, p_xt);
    // 2. qkv_nd[n,o] = x_nd · qkv_w^T + b   (bias per-col)
    mma_gemm<<<dim3(QKVD / 128, NPOS / 128, BATCH), 256>>>(
        p_xt, qkv_w, qkv_b, p_qkv, 256, DIM, DIM, QKVD,
        (long long)NPOS * DIM, 0LL, (long long)NPOS * QKVD, 1, 1);
    // 3. featmap q (in place), featmap+transpose k -> k_dn, transpose v -> v_dn
    featmap_tr<<<dim3(NPOS / 32, 3, BATCH), 256>>>(p_qkv, p_kdn, p_vdn);
    // 4. kmean, z
    kmean_k<<<dim3(DIM, BATCH), 256>>>(p_kdn, p_km);
    zcalc<<<dim3(NPOS / 8, BATCH), 256>>>(p_qkv, p_km, p_z);
    // 5. vkT = v_dn · k_dn^T / N  (split-K x4)
    mma_gemm<<<dim3(2, 2, BATCH * 4), 256>>>(
        p_vdn, p_kdn, nullptr, p_part, 1024, NPOS, NPOS, DIM,
        (long long)DIM * NPOS, (long long)DIM * NPOS, (long long)DIM * DIM, 4, 0);
    vkt_reduce<<<dim3(BATCH * DIM * DIM / 256), 256>>>(p_part, p_vkT);
    // 6. depthwise conv
    dwconv_kernel<<<dim3(DIM, BATCH), 256>>>(p_vdn, dwc_w, dwc_b, p_dw);
    // 7. attn_dn[i,n] = vkT · q_nd^T
    mma_gemm<<<dim3(NPOS / 128, 2, BATCH), 256>>>(
        p_vkT, p_qkv, nullptr, p_attn, 256, DIM, QKVD, NPOS,
        (long long)DIM * DIM, (long long)NPOS * QKVD, (long long)DIM * NPOS, 1, 0);
    // 8. normalize + add dw -> y_nd
    attn_norm<<<dim3(NPOS / 32, BATCH), dim3(32, 8)>>>(p_attn, p_dw, p_z, norm_w, p_y);
    // 9. out[c,n] = proj_w · y_nd^T + proj_b  (bias per-row)
    mma_gemm<<<dim3(NPOS / 128, 2, BATCH), 256>>>(
        proj_w, p_y, proj_b, out, 256, DIM, DIM, NPOS,
        0LL, (long long)NPOS * DIM, (long long)DIM * NPOS, 1, 2);
}

// round 7
// speedup vs baseline: 4.3031x; 1.6169x over previous
#include <cuda_runtime.h>
#include <cstdint>

#define BATCH 16
#define DIM   256
#define NPOS  4096
#define QKVD  768
#define HH    64
#define WW    64
#define EPSF  1e-5f

// ---------------- scratch ----------------
__device__ float g_xt [(size_t)BATCH * NPOS * DIM];    // x^T [b][n][c], tf32-rounded
__device__ float g_qkv[(size_t)BATCH * NPOS * QKVD];   // [b][n][768]
__device__ float g_kdn[(size_t)BATCH * DIM * NPOS];    // featmapped k [b][d][n]
__device__ float g_vdn[(size_t)BATCH * DIM * NPOS];    // v [b][d][n]
__device__ float g_vkT[(size_t)BATCH * DIM * DIM];
__device__ float g_part[(size_t)BATCH * 8 * DIM * DIM];
__device__ float g_attn[(size_t)BATCH * DIM * NPOS];
__device__ float g_dw [(size_t)BATCH * DIM * NPOS];
__device__ float g_y  [(size_t)BATCH * NPOS * DIM];
__device__ float g_z  [(size_t)BATCH * NPOS];
__device__ float g_kmean[BATCH * DIM];
__device__ float g_qw[QKVD * DIM];
__device__ float g_pw[DIM * DIM];

__device__ __forceinline__ uint32_t f2tf32(float v) {
    uint32_t u;
    asm("cvt.rn.tf32.f32 %0, %1;" : "=r"(u) : "f"(v));
    return u;
}
__device__ __forceinline__ float tf32r(float v) { return __uint_as_float(f2tf32(v)); }

__device__ __forceinline__ void cp16(uint32_t smem, const float* g) {
    asm volatile("cp.async.cg.shared.global [%0], [%1], 16;" :: "r"(smem), "l"(g));
}
#define CP_COMMIT() asm volatile("cp.async.commit_group;" ::: "memory")
#define CP_WAIT1()  asm volatile("cp.async.wait_group 1;" ::: "memory")

// ---------------- tf32 mma.sync GEMM, cp.async 3-stage: D[128m x 128n] = A[m,K]·B[n,K]^T ----------------
// A,B row-major K-contiguous, PRE-ROUNDED to tf32. 256 threads. biasMode: 0 none, 1 per-col, 2 per-row.
#define STG_W 2560              // 128 rows * 20 words per stage
__global__ __launch_bounds__(256)
void mma_gemm(const float* __restrict__ A, const float* __restrict__ B,
              const float* __restrict__ bias, float* __restrict__ C,
              int K, int ldA, int ldB, int ldC,
              long long aStride, long long bStride, long long cStride,
              int kChunks, int biasMode)
{
    extern __shared__ float sm[];
    float* smA = sm;                  // 3 stages
    float* smB = sm + 3 * STG_W;

    int z = blockIdx.z;
    int b = z / kChunks, chunk = z - b * kChunks;
    int m0 = blockIdx.y * 128, n0 = blockIdx.x * 128;
    const float* Ab = A + (size_t)b * aStride + (size_t)m0 * ldA + (size_t)chunk * K;
    const float* Bb = B + (size_t)b * bStride + (size_t)n0 * ldB + (size_t)chunk * K;
    float* Cb = C + (size_t)z * cStride;

    int tid = threadIdx.x;
    int lane = tid & 31, wid = tid >> 5;
    int g = lane >> 2, tig = lane & 3;
    int warp_m = (wid & 1) * 64, warp_n = (wid >> 1) * 32;

    // loader mapping: thread covers rows lr0 and lr0+64, 16B chunk at k-offset lko
    int lr0 = tid >> 2;
    int lko = (tid & 3) * 4;
    uint32_t sbase;
    asm("{ .reg .u64 t; cvta.to.shared.u64 t, %1; cvt.u32.u64 %0, t; }" : "=r"(sbase) : "l"(sm));
    uint32_t aoff0 = (uint32_t)(lr0 * 20 + lko) * 4;
    uint32_t aoff1 = (uint32_t)((lr0 + 64) * 20 + lko) * 4;
    const uint32_t STG_B = STG_W * 4;
    uint32_t sA = sbase, sB = sbase + 3 * STG_B;

    const float* ag0 = Ab + (size_t)lr0 * ldA + lko;
    const float* ag1 = Ab + (size_t)(lr0 + 64) * ldA + lko;
    const float* bg0 = Bb + (size_t)lr0 * ldB + lko;
    const float* bg1 = Bb + (size_t)(lr0 + 64) * ldB + lko;

    int S = K >> 4;

    float acc[4][4][4];
#pragma unroll
    for (int i = 0; i < 4; ++i)
#pragma unroll
        for (int j = 0; j < 4; ++j)
#pragma unroll
            for (int r = 0; r < 4; ++r) acc[i][j][r] = 0.f;

    // prologue: stages 0,1
    {
        cp16(sA + aoff0, ag0); cp16(sA + aoff1, ag1);
        cp16(sB + aoff0, bg0); cp16(sB + aoff1, bg1);
        CP_COMMIT();
        cp16(sA + STG_B + aoff0, ag0 + 16); cp16(sA + STG_B + aoff1, ag1 + 16);
        cp16(sB + STG_B + aoff0, bg0 + 16); cp16(sB + STG_B + aoff1, bg1 + 16);
        CP_COMMIT();
    }

    for (int s = 0; s < S; ++s) {
        CP_WAIT1();
        __syncthreads();
        if (s + 2 < S) {
            int buf2 = (s + 2) % 3;
            int kc = (s + 2) * 16;
            cp16(sA + buf2 * STG_B + aoff0, ag0 + kc);
            cp16(sA + buf2 * STG_B + aoff1, ag1 + kc);
            cp16(sB + buf2 * STG_B + aoff0, bg0 + kc);
            cp16(sB + buf2 * STG_B + aoff1, bg1 + kc);
        }
        CP_COMMIT();
        const float* As_ = smA + (s % 3) * STG_W;
        const float* Bs_ = smB + (s % 3) * STG_W;
#pragma unroll
        for (int kb = 0; kb < 16; kb += 8) {
            uint32_t af[4][4], bf[4][2];
#pragma unroll
            for (int i = 0; i < 4; ++i) {
                int r0 = warp_m + i * 16 + g;
                af[i][0] = __float_as_uint(As_[r0 * 20 + kb + tig]);
                af[i][1] = __float_as_uint(As_[(r0 + 8) * 20 + kb + tig]);
                af[i][2] = __float_as_uint(As_[r0 * 20 + kb + tig + 4]);
                af[i][3] = __float_as_uint(As_[(r0 + 8) * 20 + kb + tig + 4]);
            }
#pragma unroll
            for (int j = 0; j < 4; ++j) {
                int c0 = warp_n + j * 8 + g;
                bf[j][0] = __float_as_uint(Bs_[c0 * 20 + kb + tig]);
                bf[j][1] = __float_as_uint(Bs_[c0 * 20 + kb + tig + 4]);
            }
#pragma unroll
            for (int i = 0; i < 4; ++i)
#pragma unroll
                for (int j = 0; j < 4; ++j)
                    asm volatile(
                        "mma.sync.aligned.m16n8k8.row.col.f32.tf32.tf32.f32 "
                        "{%0,%1,%2,%3}, {%4,%5,%6,%7}, {%8,%9}, {%0,%1,%2,%3};"
                        : "+f"(acc[i][j][0]), "+f"(acc[i][j][1]),
                          "+f"(acc[i][j][2]), "+f"(acc[i][j][3])
                        : "r"(af[i][0]), "r"(af[i][1]), "r"(af[i][2]), "r"(af[i][3]),
                          "r"(bf[j][0]), "r"(bf[j][1]));
        }
    }

    // epilogue
#pragma unroll
    for (int i = 0; i < 4; ++i) {
        int row0 = m0 + warp_m + i * 16 + g;
        float br0 = 0.f, br1 = 0.f;
        if (biasMode == 2) { br0 = bias[row0]; br1 = bias[row0 + 8]; }
#pragma unroll
        for (int j = 0; j < 4; ++j) {
            int col = n0 + warp_n + j * 8 + tig * 2;
            float bc0 = 0.f, bc1 = 0.f;
            if (biasMode == 1) { bc0 = bias[col]; bc1 = bias[col + 1]; }
            else if (biasMode == 2) { bc0 = br0; bc1 = br0; }
            float2 v0 = make_float2(acc[i][j][0] + bc0, acc[i][j][1] + bc1);
            if (biasMode == 2) { bc0 = br1; bc1 = br1; }
            float2 v1 = make_float2(acc[i][j][2] + bc0, acc[i][j][3] + bc1);
            *(float2*)&Cb[(size_t)row0 * ldC + col] = v0;
            *(float2*)&Cb[(size_t)(row0 + 8) * ldC + col] = v1;
        }
    }
}

// ---------------- round-copy weights to tf32 ----------------
__global__ void round_copy(const float* __restrict__ in, float* __restrict__ out, int n)
{
    int i = blockIdx.x * 256 + threadIdx.x;
    if (i < n) out[i] = tf32r(in[i]);
}

// ---------------- transpose x [c,n] -> [n,c], tf32-rounded ----------------
__global__ void transpose_x(const float* __restrict__ x, float* __restrict__ xt)
{
    __shared__ float t[32][33];
    int b = blockIdx.z;
    int n0 = blockIdx.x * 32, c0 = blockIdx.y * 32;
    const float* xb = x + (size_t)b * DIM * NPOS;
    float* xo = xt + (size_t)b * NPOS * DIM;
    int tx = threadIdx.x, ty = threadIdx.y;
#pragma unroll
    for (int j = 0; j < 4; ++j)
        t[ty + j * 8][tx] = xb[(size_t)(c0 + ty + j * 8) * NPOS + n0 + tx];
    __syncthreads();
#pragma unroll
    for (int j = 0; j < 4; ++j)
        xo[(size_t)(n0 + ty + j * 8) * DIM + c0 + tx] = tf32r(t[tx][ty + j * 8]);
}

// ---------------- featmap (q in-place; k featmap+transpose; v transpose), tf32-rounded writes ----------------
__global__ void featmap_tr(float* __restrict__ qkv, float* __restrict__ kdn, float* __restrict__ vdn)
{
    __shared__ float t[32][257];
    int mode = blockIdx.y;             // 0=q, 1=k, 2=v
    int b = blockIdx.z;
    int n0 = blockIdx.x * 32;
    int tid = threadIdx.x, wid = tid >> 5, lid = tid & 31;
    float* base = qkv + (size_t)b * NPOS * QKVD + mode * 256;

#pragma unroll
    for (int rr = 0; rr < 4; ++rr) {
        int n = wid * 4 + rr;
        float* rp = base + (size_t)(n0 + n) * QKVD;
        float v[8];
        float ss = 0.f;
#pragma unroll
        for (int j = 0; j < 8; ++j) {
            float u = rp[lid + 32 * j];
            if (mode < 2) {
                u = fmaxf(u, 0.f) + EPSF;
                u = u * u;
                ss += u * u;
            }
            v[j] = u;
        }
        if (mode < 2) {
#pragma unroll
            for (int o = 16; o > 0; o >>= 1) ss += __shfl_xor_sync(0xFFFFFFFFu, ss, o);
            float inv = 1.f / fmaxf(sqrtf(ss), 1e-12f);
#pragma unroll
            for (int j = 0; j < 8; ++j) v[j] *= inv;
        }
        if (mode == 0) {
#pragma unroll
            for (int j = 0; j < 8; ++j) rp[lid + 32 * j] = tf32r(v[j]);
        } else {
#pragma unroll
            for (int j = 0; j < 8; ++j) t[n][lid + 32 * j] = tf32r(v[j]);
        }
    }
    if (mode == 0) return;
    __syncthreads();
    float* out = (mode == 1 ? kdn : vdn) + (size_t)b * DIM * NPOS;
    float* op = out + (size_t)tid * NPOS + n0;
#pragma unroll
    for (int nn = 0; nn < 32; nn += 4)
        *(float4*)&op[nn] = make_float4(t[nn][tid], t[nn + 1][tid], t[nn + 2][tid], t[nn + 3][tid]);
}

// ---------------- kmean over n of k_dn ----------------
__global__ void kmean_k(const float* __restrict__ kdn, float* __restrict__ km)
{
    int d = blockIdx.x, b = blockIdx.y;
    const float4* kp = (const float4*)(kdn + ((size_t)b * DIM + d) * NPOS);
    float s = 0.f;
    for (int i = threadIdx.x; i < NPOS / 4; i += 256) {
        float4 v = kp[i];
        s += (v.x + v.y) + (v.z + v.w);
    }
    __shared__ float red[256];
    red[threadIdx.x] = s;
    __syncthreads();
    for (int st = 128; st > 0; st >>= 1) {
        if (threadIdx.x < st) red[threadIdx.x] += red[threadIdx.x + st];
        __syncthreads();
    }
    if (threadIdx.x == 0) km[b * DIM + d] = red[0] * (1.f / (float)NPOS);
}

// ---------------- z[b][n] = kmean · q_nd[n] + eps ----------------
__global__ void zcalc(const float* __restrict__ qkv, const float* __restrict__ km, float* __restrict__ zo)
{
    __shared__ float kms[256];
    int b = blockIdx.y;
    int tid = threadIdx.x, wid = tid >> 5, lid = tid & 31;
    kms[tid] = km[b * DIM + tid];
    __syncthreads();
    int n = blockIdx.x * 8 + wid;
    const float* qp = qkv + ((size_t)b * NPOS + n) * QKVD;
    float s = 0.f;
#pragma unroll
    for (int j = 0; j < 8; ++j) s += kms[lid + 32 * j] * qp[lid + 32 * j];
#pragma unroll
    for (int o = 16; o > 0; o >>= 1) s += __shfl_xor_sync(0xFFFFFFFFu, s, o);
    if (lid == 0) zo[(size_t)b * NPOS + n] = s + EPSF;
}

// ---------------- vkt reduce (8 split-K chunks) + 1/N scale, tf32-rounded ----------------
__global__ void vkt_reduce(const float* __restrict__ part, float* __restrict__ vkT)
{
    int idx = blockIdx.x * 256 + threadIdx.x;
    int b = idx >> 16, ij = idx & 65535;
    float s = 0.f;
#pragma unroll
    for (int c = 0; c < 8; ++c) s += part[(size_t)(b * 8 + c) * 65536 + ij];
    vkT[idx] = tf32r(s * (1.f / (float)NPOS));
}

// ---------------- depthwise 5x5 on v_dn -> dw_dn ----------------
__global__ void dwconv_kernel(const float* __restrict__ vdn, const float* __restrict__ w,
                              const float* __restrict__ bias, float* __restrict__ dw)
{
    int ch = blockIdx.x, b = blockIdx.y;
    const float* vp = vdn + ((size_t)b * DIM + ch) * NPOS;
    __shared__ float sm[68][68];
    __shared__ float ws[25];
    int tid = threadIdx.x;
    if (tid < 25) ws[tid] = w[ch * 25 + tid];
    for (int idx = tid; idx < 68 * 68; idx += 256) {
        int r = idx / 68, c = idx % 68;
        int gr = r - 2, gc = c - 2;
        sm[r][c] = (gr >= 0 && gr < HH && gc >= 0 && gc < WW) ? vp[gr * WW + gc] : 0.f;
    }
    __syncthreads();
    float bv = bias[ch];
    for (int p = tid; p < NPOS; p += 256) {
        int py = p >> 6, px = p & 63;
        float acc = bv;
#pragma unroll
        for (int ky = 0; ky < 5; ++ky)
#pragma unroll
            for (int kx = 0; kx < 5; ++kx)
                acc += sm[py + ky][px + kx] * ws[ky * 5 + kx];
        dw[((size_t)b * DIM + ch) * NPOS + p] = acc;
    }
}

// ---------------- attn/z/RMS/norm_w + dw  ->  y_nd (tf32-rounded) ----------------
__global__ void attn_norm(const float* __restrict__ attn, const float* __restrict__ dw,
                          const float* __restrict__ zbuf, const float* __restrict__ norm_w,
                          float* __restrict__ y)
{
    int b = blockIdx.y;
    int n0 = blockIdx.x * 32;
    int tx = threadIdx.x, ty = threadIdx.y;
    int tid = ty * 32 + tx;
    int n = n0 + tx;
    __shared__ float nw[256];
    __shared__ float red[8][33];
    __shared__ float rr[32];
    nw[tid] = norm_w[tid];
    __syncthreads();
    const float* ap = attn + (size_t)b * DIM * NPOS;
    const float* dp = dw + (size_t)b * DIM * NPOS;
    float invz = 1.f / zbuf[(size_t)b * NPOS + n];
    float t[32];
    float ss = 0.f;
#pragma unroll
    for (int r = 0; r < 32; ++r) {
        int i = ty * 32 + r;
        t[r] = ap[(size_t)i * NPOS + n] * invz;
        ss += t[r] * t[r];
    }
    red[ty][tx] = ss;
    __syncthreads();
    if (ty == 0) {
        float s = 0.f;
#pragma unroll
        for (int k = 0; k < 8; ++k) s += red[k][tx];
        rr[tx] = rsqrtf(s * (1.f / (float)DIM) + EPSF);
    }
    __syncthreads();
    float ri = rr[tx];
    float* yp = y + ((size_t)b * NPOS + n) * DIM + ty * 32;
#pragma unroll
    for (int r = 0; r < 32; r += 4) {
        float4 o;
        o.x = tf32r(t[r + 0] * ri * nw[ty * 32 + r + 0] + dp[(size_t)(ty * 32 + r + 0) * NPOS + n]);
        o.y = tf32r(t[r + 1] * ri * nw[ty * 32 + r + 1] + dp[(size_t)(ty * 32 + r + 1) * NPOS + n]);
        o.z = tf32r(t[r + 2] * ri * nw[ty * 32 + r + 2] + dp[(size_t)(ty * 32 + r + 2) * NPOS + n]);
        o.w = tf32r(t[r + 3] * ri * nw[ty * 32 + r + 3] + dp[(size_t)(ty * 32 + r + 3) * NPOS + n]);
        *(float4*)&yp[r] = o;
    }
}

// ---------------- host ----------------
extern "C" void kernel_launch(void* const* d_in, const int* in_sizes, int n_in,
                              void* d_out, int out_size)
{
    const float* x      = (const float*)d_in[0];
    const float* qkv_w  = (const float*)d_in[1];
    const float* qkv_b  = (const float*)d_in[2];
    const float* dwc_w  = (const float*)d_in[3];
    const float* dwc_b  = (const float*)d_in[4];
    const float* norm_w = (const float*)d_in[5];
    const float* proj_w = (const float*)d_in[6];
    const float* proj_b = (const float*)d_in[7];
    float* out = (float*)d_out;

    float *p_xt, *p_qkv, *p_kdn, *p_vdn, *p_vkT, *p_part, *p_attn, *p_dw, *p_y, *p_z, *p_km, *p_qw, *p_pw;
    cudaGetSymbolAddress((void**)&p_xt, g_xt);
    cudaGetSymbolAddress((void**)&p_qkv, g_qkv);
    cudaGetSymbolAddress((void**)&p_kdn, g_kdn);
    cudaGetSymbolAddress((void**)&p_vdn, g_vdn);
    cudaGetSymbolAddress((void**)&p_vkT, g_vkT);
    cudaGetSymbolAddress((void**)&p_part, g_part);
    cudaGetSymbolAddress((void**)&p_attn, g_attn);
    cudaGetSymbolAddress((void**)&p_dw, g_dw);
    cudaGetSymbolAddress((void**)&p_y, g_y);
    cudaGetSymbolAddress((void**)&p_z, g_z);
    cudaGetSymbolAddress((void**)&p_km, g_kmean);
    cudaGetSymbolAddress((void**)&p_qw, g_qw);
    cudaGetSymbolAddress((void**)&p_pw, g_pw);

    const int SMEM = 6 * STG_W * 4;   // 61440
    cudaFuncSetAttribute(mma_gemm, cudaFuncAttributeMaxDynamicSharedMemorySize, SMEM);

    // 1. x -> x_nd (rounded)
    transpose_x<<<dim3(NPOS / 32, DIM / 32, BATCH), dim3(32, 8)>>>(x, p_xt);
    // 2,3. round weights
    round_copy<<<(QKVD * DIM + 255) / 256, 256>>>(qkv_w, p_qw, QKVD * DIM);
    round_copy<<<(DIM * DIM + 255) / 256, 256>>>(proj_w, p_pw, DIM * DIM);
    // 4. qkv_nd[n,o] = x_nd · qkv_w^T + b   (profiled slot)
    mma_gemm<<<dim3(QKVD / 128, NPOS / 128, BATCH), 256, SMEM>>>(
        p_xt, p_qw, qkv_b, p_qkv, 256, DIM, DIM, QKVD,
        (long long)NPOS * DIM, 0LL, (long long)NPOS * QKVD, 1, 1);
    // 5. featmap q (in place), k -> k_dn, v -> v_dn
    featmap_tr<<<dim3(NPOS / 32, 3, BATCH), 256>>>(p_qkv, p_kdn, p_vdn);
    // 6,7. kmean, z
    kmean_k<<<dim3(DIM, BATCH), 256>>>(p_kdn, p_km);
    zcalc<<<dim3(NPOS / 8, BATCH), 256>>>(p_qkv, p_km, p_z);
    // 8,9. vkT = v_dn · k_dn^T / N  (split-K x8)
    mma_gemm<<<dim3(2, 2, BATCH * 8), 256, SMEM>>>(
        p_vdn, p_kdn, nullptr, p_part, 512, NPOS, NPOS, DIM,
        (long long)DIM * NPOS, (long long)DIM * NPOS, (long long)DIM * DIM, 8, 0);
    vkt_reduce<<<dim3(BATCH * DIM * DIM / 256), 256>>>(p_part, p_vkT);
    // 10. depthwise conv
    dwconv_kernel<<<dim3(DIM, BATCH), 256>>>(p_vdn, dwc_w, dwc_b, p_dw);
    // 11. attn_dn = vkT · q_nd^T
    mma_gemm<<<dim3(NPOS / 128, 2, BATCH), 256, SMEM>>>(
        p_vkT, p_qkv, nullptr, p_attn, 256, DIM, QKVD, NPOS,
        (long long)DIM * DIM, (long long)NPOS * QKVD, (long long)DIM * NPOS, 1, 0);
    // 12. normalize + add dw -> y_nd
    attn_norm<<<dim3(NPOS / 32, BATCH), dim3(32, 8)>>>(p_attn, p_dw, p_z, norm_w, p_y);
    // 13. out = proj_w · y_nd^T + proj_b
    mma_gemm<<<dim3(NPOS / 128, 2, BATCH), 256, SMEM>>>(
        p_pw, p_y, proj_b, out, 256, DIM, DIM, NPOS,
        0LL, (long long)NPOS * DIM, (long long)DIM * NPOS, 1, 2);
}

// round 9
// speedup vs baseline: 4.4448x; 1.0329x over previous
#include <cuda_runtime.h>
#include <cstdint>

#define BATCH 16
#define DIM   256
#define NPOS  4096
#define QKVD  768
#define HH    64
#define WW    64
#define EPSF  1e-5f

// ---------------- scratch ----------------
__device__ float g_x  [(size_t)BATCH * DIM * NPOS];    // tf32-rounded x [b][c][n]
__device__ float g_qkv[(size_t)BATCH * QKVD * NPOS];   // [b][768][n]: q 0-255, k 256-511, v 512-767
__device__ float g_vkT[(size_t)BATCH * DIM * DIM];
__device__ float g_part[(size_t)BATCH * 8 * DIM * DIM];
__device__ float g_dw [(size_t)BATCH * DIM * NPOS];    // [b][d][n]
__device__ float g_y  [(size_t)BATCH * DIM * NPOS];    // [b][d][n]
__device__ float g_z  [(size_t)BATCH * NPOS];
__device__ float g_kmean[BATCH * DIM];
__device__ float g_qw[QKVD * DIM];
__device__ float g_pw[DIM * DIM];

__device__ __forceinline__ uint32_t f2tf32(float v) {
    uint32_t u;
    asm("cvt.rn.tf32.f32 %0, %1;" : "=r"(u) : "f"(v));
    return u;
}
__device__ __forceinline__ float tf32r(float v) { return __uint_as_float(f2tf32(v)); }

__device__ __forceinline__ void cp16(uint32_t smem, const float* g) {
    asm volatile("cp.async.cg.shared.global [%0], [%1], 16;" :: "r"(smem), "l"(g));
}
#define CP_COMMIT() asm volatile("cp.async.commit_group;" ::: "memory")
#define CP_WAIT1()  asm volatile("cp.async.wait_group 1;" ::: "memory")

#define MMA_TF32(acc, a0, a1, a2, a3, b0, b1) \
    asm volatile("mma.sync.aligned.m16n8k8.row.col.f32.tf32.tf32.f32 " \
                 "{%0,%1,%2,%3}, {%4,%5,%6,%7}, {%8,%9}, {%0,%1,%2,%3};" \
                 : "+f"((acc)[0]), "+f"((acc)[1]), "+f"((acc)[2]), "+f"((acc)[3]) \
                 : "r"(a0), "r"(a1), "r"(a2), "r"(a3), "r"(b0), "r"(b1))

// ---------------- tf32 mma.sync GEMM, cp.async 3-stage: C[128m x 128n] = A[m,K]·Bop ----------------
// A row-major K-contiguous, pre-rounded tf32. If bTrans==0: B row-major [n][K]. If bTrans==1:
// B is [K][Ntotal] (n-contiguous) and tiles are transposed on load. 256 threads.
// biasMode: 0 none, 2 per-row(m). roundC: tf32-round outputs.
#define STG_W 2560              // A stage: 128 rows * 20 words; B stage <= 2560
__global__ __launch_bounds__(256)
void mma_gemm(const float* __restrict__ A, const float* __restrict__ B,
              const float* __restrict__ bias, float* __restrict__ C,
              int K, int ldA, int ldB, int ldC,
              long long aStride, long long bStride, long long cStride,
              int kChunks, int biasMode, int bTrans, int roundC)
{
    extern __shared__ float sm[];
    float* smA = sm;
    float* smB = sm + 3 * STG_W;

    int z = blockIdx.z;
    int b = z / kChunks, chunk = z - b * kChunks;
    int kStart = chunk * K;
    int m0 = blockIdx.y * 128, n0 = blockIdx.x * 128;
    const float* Ab = A + (size_t)b * aStride + (size_t)m0 * ldA + kStart;
    float* Cb = C + (size_t)z * cStride;

    int tid = threadIdx.x;
    int lane = tid & 31, wid = tid >> 5;
    int g = lane >> 2, tig = lane & 3;
    int warp_m = (wid & 1) * 64, warp_n = (wid >> 1) * 32;

    uint32_t sbase;
    asm("{ .reg .u64 t; cvta.to.shared.u64 t, %1; cvt.u32.u64 %0, t; }" : "=r"(sbase) : "l"(sm));
    const uint32_t STG_B = STG_W * 4;
    uint32_t sA = sbase, sB = sbase + 3 * STG_B;

    // A loader: rows lr0, lr0+64; 16B chunk at k-offset lko
    int lr0 = tid >> 2;
    int lko = (tid & 3) * 4;
    uint32_t aoff0 = (uint32_t)(lr0 * 20 + lko) * 4;
    uint32_t aoff1 = (uint32_t)((lr0 + 64) * 20 + lko) * 4;
    const float* ag0 = Ab + (size_t)lr0 * ldA + lko;
    const float* ag1 = Ab + (size_t)(lr0 + 64) * ldA + lko;

    // B loaders
    const float* bg0 = nullptr; const float* bg1 = nullptr;   // non-trans
    uint32_t boff0 = 0, boff1 = 0;
    const float* btg = nullptr;                               // trans
    int tkr0 = 0, tkr1 = 0, tco0 = 0, tco1 = 0;
    uint32_t toff0 = 0, toff1 = 0;
    if (!bTrans) {
        const float* Bb = B + (size_t)b * bStride + (size_t)n0 * ldB + kStart;
        bg0 = Bb + (size_t)lr0 * ldB + lko;
        bg1 = Bb + (size_t)(lr0 + 64) * ldB + lko;
        boff0 = aoff0; boff1 = aoff1;
    } else {
        btg = B + (size_t)b * bStride + (size_t)kStart * ldB + n0;
        int c0 = tid, c1 = tid + 256;
        tkr0 = c0 >> 5; tco0 = (c0 & 31) * 4;
        tkr1 = c1 >> 5; tco1 = (c1 & 31) * 4;
        toff0 = (uint32_t)(tkr0 * 132 + tco0) * 4;
        toff1 = (uint32_t)(tkr1 * 132 + tco1) * 4;
    }

    int S = K >> 4;

    float acc[4][4][4];
#pragma unroll
    for (int i = 0; i < 4; ++i)
#pragma unroll
        for (int j = 0; j < 4; ++j)
#pragma unroll
            for (int r = 0; r < 4; ++r) acc[i][j][r] = 0.f;

    // prologue: stages 0,1
#pragma unroll
    for (int ps = 0; ps < 2; ++ps) {
        int kc = ps * 16;
        uint32_t so = ps * STG_B;
        cp16(sA + so + aoff0, ag0 + kc);
        cp16(sA + so + aoff1, ag1 + kc);
        if (!bTrans) {
            cp16(sB + so + boff0, bg0 + kc);
            cp16(sB + so + boff1, bg1 + kc);
        } else {
            cp16(sB + so + toff0, btg + (size_t)(kc + tkr0) * ldB + tco0);
            cp16(sB + so + toff1, btg + (size_t)(kc + tkr1) * ldB + tco1);
        }
        CP_COMMIT();
    }

    for (int s = 0; s < S; ++s) {
        CP_WAIT1();
        __syncthreads();
        if (s + 2 < S) {
            int buf2 = (s + 2) % 3;
            int kc = (s + 2) * 16;
            uint32_t so = buf2 * STG_B;
            cp16(sA + so + aoff0, ag0 + kc);
            cp16(sA + so + aoff1, ag1 + kc);
            if (!bTrans) {
                cp16(sB + so + boff0, bg0 + kc);
                cp16(sB + so + boff1, bg1 + kc);
            } else {
                cp16(sB + so + toff0, btg + (size_t)(kc + tkr0) * ldB + tco0);
                cp16(sB + so + toff1, btg + (size_t)(kc + tkr1) * ldB + tco1);
            }
        }
        CP_COMMIT();
        const float* As_ = smA + (s % 3) * STG_W;
        const float* Bs_ = smB + (s % 3) * STG_W;
#pragma unroll
        for (int kb = 0; kb < 16; kb += 8) {
            uint32_t af[4][4], bf[4][2];
#pragma unroll
            for (int i = 0; i < 4; ++i) {
                int r0 = warp_m + i * 16 + g;
                af[i][0] = __float_as_uint(As_[r0 * 20 + kb + tig]);
                af[i][1] = __float_as_uint(As_[(r0 + 8) * 20 + kb + tig]);
                af[i][2] = __float_as_uint(As_[r0 * 20 + kb + tig + 4]);
                af[i][3] = __float_as_uint(As_[(r0 + 8) * 20 + kb + tig + 4]);
            }
            if (!bTrans) {
#pragma unroll
                for (int j = 0; j < 4; ++j) {
                    int c0 = warp_n + j * 8 + g;
                    bf[j][0] = __float_as_uint(Bs_[c0 * 20 + kb + tig]);
                    bf[j][1] = __float_as_uint(Bs_[c0 * 20 + kb + tig + 4]);
                }
            } else {
#pragma unroll
                for (int j = 0; j < 4; ++j) {
                    int c0 = warp_n + j * 8 + g;
                    bf[j][0] = __float_as_uint(Bs_[(kb + tig) * 132 + c0]);
                    bf[j][1] = __float_as_uint(Bs_[(kb + tig + 4) * 132 + c0]);
                }
            }
#pragma unroll
            for (int i = 0; i < 4; ++i)
#pragma unroll
                for (int j = 0; j < 4; ++j)
                    MMA_TF32(acc[i][j], af[i][0], af[i][1], af[i][2], af[i][3], bf[j][0], bf[j][1]);
        }
    }

    // epilogue
#pragma unroll
    for (int i = 0; i < 4; ++i) {
        int row0 = m0 + warp_m + i * 16 + g;
        float br0 = (biasMode == 2) ? bias[row0] : 0.f;
        float br1 = (biasMode == 2) ? bias[row0 + 8] : 0.f;
#pragma unroll
        for (int j = 0; j < 4; ++j) {
            int col = n0 + warp_n + j * 8 + tig * 2;
            float2 v0 = make_float2(acc[i][j][0] + br0, acc[i][j][1] + br0);
            float2 v1 = make_float2(acc[i][j][2] + br1, acc[i][j][3] + br1);
            if (roundC) {
                v0.x = tf32r(v0.x); v0.y = tf32r(v0.y);
                v1.x = tf32r(v1.x); v1.y = tf32r(v1.y);
            }
            *(float2*)&Cb[(size_t)row0 * ldC + col] = v0;
            *(float2*)&Cb[(size_t)(row0 + 8) * ldC + col] = v1;
        }
    }
}

// ---------------- fused attn: y[d][n] = RMSNorm((vkT·q)/z)*nw + dw.  M=256, 512 threads ----------------
#define A_STG 5120   // 256 rows * 20 words
#define B_STG 2112   // 16 k-rows * 132 words
#define EPI_W (3 * A_STG + 3 * B_STG)
__global__ __launch_bounds__(512)
void attn_fused(const float* __restrict__ vkT, const float* __restrict__ q,
                const float* __restrict__ zbuf, const float* __restrict__ dw,
                const float* __restrict__ norm_w, float* __restrict__ y)
{
    extern __shared__ float sm[];
    float* smA = sm;
    float* smB = sm + 3 * A_STG;
    float* nw  = sm + EPI_W;           // 256
    float* ssq = nw + 256;             // 4*132
    float* rr  = ssq + 4 * 132;        // 128

    int b = blockIdx.z;
    int n0 = blockIdx.x * 128;
    const float* Ab = vkT + (size_t)b * DIM * DIM;
    const float* qg = q + (size_t)b * QKVD * NPOS + n0;
    const float* dp = dw + (size_t)b * DIM * NPOS;
    float* yp = y + (size_t)b * DIM * NPOS;

    int tid = threadIdx.x;
    int lane = tid & 31, wid = tid >> 5;
    int g = lane >> 2, tig = lane & 3;
    int warp_m = (wid & 3) * 64, warp_n = (wid >> 2) * 32;

    if (tid < 256) nw[tid] = norm_w[tid];

    uint32_t sbase;
    asm("{ .reg .u64 t; cvta.to.shared.u64 t, %1; cvt.u32.u64 %0, t; }" : "=r"(sbase) : "l"(sm));
    uint32_t sA = sbase, sB = sbase + 3 * A_STG * 4;

    // A loader: 1024 chunks / 512 thr = 2 each
    int ac0 = tid, ac1 = tid + 512;
    int ar0 = ac0 >> 2, ako0 = (ac0 & 3) * 4;
    int ar1 = ac1 >> 2, ako1 = (ac1 & 3) * 4;
    uint32_t aoff0 = (uint32_t)(ar0 * 20 + ako0) * 4;
    uint32_t aoff1 = (uint32_t)(ar1 * 20 + ako1) * 4;
    // B loader: 512 chunks, 1 each (transposed tile of q [d][n])
    int bkr = tid >> 5, bco = (tid & 31) * 4;
    uint32_t boff = (uint32_t)(bkr * 132 + bco) * 4;

#pragma unroll
    for (int ps = 0; ps < 2; ++ps) {
        int kc = ps * 16;
        cp16(sA + ps * A_STG * 4 + aoff0, Ab + (size_t)ar0 * DIM + kc + ako0);
        cp16(sA + ps * A_STG * 4 + aoff1, Ab + (size_t)ar1 * DIM + kc + ako1);
        cp16(sB + ps * B_STG * 4 + boff, qg + (size_t)(kc + bkr) * NPOS + bco);
        CP_COMMIT();
    }

    float acc[4][4][4];
#pragma unroll
    for (int i = 0; i < 4; ++i)
#pragma unroll
        for (int j = 0; j < 4; ++j)
#pragma unroll
            for (int r = 0; r < 4; ++r) acc[i][j][r] = 0.f;

    const int S = 16;   // K = 256
    for (int s = 0; s < S; ++s) {
        CP_WAIT1();
        __syncthreads();
        if (s + 2 < S) {
            int buf2 = (s + 2) % 3;
            int kc = (s + 2) * 16;
            cp16(sA + buf2 * A_STG * 4 + aoff0, Ab + (size_t)ar0 * DIM + kc + ako0);
            cp16(sA + buf2 * A_STG * 4 + aoff1, Ab + (size_t)ar1 * DIM + kc + ako1);
            cp16(sB + buf2 * B_STG * 4 + boff, qg + (size_t)(kc + bkr) * NPOS + bco);
        }
        CP_COMMIT();
        const float* As_ = smA + (s % 3) * A_STG;
        const float* Bs_ = smB + (s % 3) * B_STG;
#pragma unroll
        for (int kb = 0; kb < 16; kb += 8) {
            uint32_t af[4][4], bf[4][2];
#pragma unroll
            for (int i = 0; i < 4; ++i) {
                int r0 = warp_m + i * 16 + g;
                af[i][0] = __float_as_uint(As_[r0 * 20 + kb + tig]);
                af[i][1] = __float_as_uint(As_[(r0 + 8) * 20 + kb + tig]);
                af[i][2] = __float_as_uint(As_[r0 * 20 + kb + tig + 4]);
                af[i][3] = __float_as_uint(As_[(r0 + 8) * 20 + kb + tig + 4]);
            }
#pragma unroll
            for (int j = 0; j < 4; ++j) {
                int c0 = warp_n + j * 8 + g;
                bf[j][0] = __float_as_uint(Bs_[(kb + tig) * 132 + c0]);
                bf[j][1] = __float_as_uint(Bs_[(kb + tig + 4) * 132 + c0]);
            }
#pragma unroll
            for (int i = 0; i < 4; ++i)
#pragma unroll
                for (int j = 0; j < 4; ++j)
                    MMA_TF32(acc[i][j], af[i][0], af[i][1], af[i][2], af[i][3], bf[j][0], bf[j][1]);
        }
    }

    // ---- fused epilogue ----
    // 1) t = acc / z ; per-column sum of squares
    float ss[8];
#pragma unroll
    for (int j = 0; j < 4; ++j) {
        int col = warp_n + j * 8 + tig * 2;
        float2 zv = *(const float2*)&zbuf[(size_t)b * NPOS + n0 + col];
        float iz0 = 1.f / zv.x, iz1 = 1.f / zv.y;
        float s0 = 0.f, s1 = 0.f;
#pragma unroll
        for (int i = 0; i < 4; ++i) {
            acc[i][j][0] *= iz0; acc[i][j][1] *= iz1;
            acc[i][j][2] *= iz0; acc[i][j][3] *= iz1;
            s0 += acc[i][j][0] * acc[i][j][0] + acc[i][j][2] * acc[i][j][2];
            s1 += acc[i][j][1] * acc[i][j][1] + acc[i][j][3] * acc[i][j][3];
        }
        ss[j * 2] = s0; ss[j * 2 + 1] = s1;
    }
    // reduce over g (lanes xor 4,8,16)
#pragma unroll
    for (int o = 4; o <= 16; o <<= 1)
#pragma unroll
        for (int c = 0; c < 8; ++c) ss[c] += __shfl_xor_sync(0xFFFFFFFFu, ss[c], o);
    __syncthreads();   // nw ready, ssq safe to write
    if (g == 0) {
        int wm = wid & 3;
#pragma unroll
        for (int j = 0; j < 4; ++j) {
            int col = warp_n + j * 8 + tig * 2;
            ssq[wm * 132 + col] = ss[j * 2];
            ssq[wm * 132 + col + 1] = ss[j * 2 + 1];
        }
    }
    __syncthreads();
    if (tid < 128) {
        float s = ssq[tid] + ssq[132 + tid] + ssq[264 + tid] + ssq[396 + tid];
        rr[tid] = rsqrtf(s * (1.f / (float)DIM) + EPSF);
    }
    __syncthreads();
    // 2) scale by rr[col]*nw[row], add dw, write y (tf32-rounded)
#pragma unroll
    for (int i = 0; i < 4; ++i) {
        int row0 = warp_m + i * 16 + g;
#pragma unroll
        for (int j = 0; j < 4; ++j) {
            int col = warp_n + j * 8 + tig * 2;
            float r0 = rr[col], r1 = rr[col + 1];
            float2 d0 = *(const float2*)&dp[(size_t)row0 * NPOS + n0 + col];
            float2 d1 = *(const float2*)&dp[(size_t)(row0 + 8) * NPOS + n0 + col];
            float2 v0, v1;
            v0.x = tf32r(acc[i][j][0] * r0 * nw[row0] + d0.x);
            v0.y = tf32r(acc[i][j][1] * r1 * nw[row0] + d0.y);
            v1.x = tf32r(acc[i][j][2] * r0 * nw[row0 + 8] + d1.x);
            v1.y = tf32r(acc[i][j][3] * r1 * nw[row0 + 8] + d1.y);
            *(float2*)&yp[(size_t)row0 * NPOS + n0 + col] = v0;
            *(float2*)&yp[(size_t)(row0 + 8) * NPOS + n0 + col] = v1;
        }
    }
}

// ---------------- round-copy to tf32 ----------------
__global__ void round_copy(const float* __restrict__ in, float* __restrict__ out, int n)
{
    int i = blockIdx.x * 256 + threadIdx.x;
    if (i < n) out[i] = tf32r(in[i]);
}

// ---------------- featmap in place on [d][n] slice ----------------
__global__ void featmap_kernel(float* __restrict__ qkv)
{
    int b = blockIdx.z;
    float* ptr = qkv + ((size_t)b * QKVD + (blockIdx.y ? 256 : 0)) * NPOS;
    int tx = threadIdx.x, ty = threadIdx.y;          // 32 x 8
    int n = blockIdx.x * 32 + tx;
    float t[32];
    float s = 0.f;
#pragma unroll
    for (int r = 0; r < 32; ++r) {
        float v = ptr[(size_t)(ty * 32 + r) * NPOS + n];
        v = fmaxf(v, 0.f) + EPSF;
        v = v * v;
        t[r] = v;
        s += v * v;
    }
    __shared__ float red[8][33];
    __shared__ float nrm[32];
    red[ty][tx] = s;
    __syncthreads();
    if (ty == 0) {
        float tot = 0.f;
#pragma unroll
        for (int k = 0; k < 8; ++k) tot += red[k][tx];
        nrm[tx] = 1.f / fmaxf(sqrtf(tot), 1e-12f);
    }
    __syncthreads();
    float inv = nrm[tx];
#pragma unroll
    for (int r = 0; r < 32; ++r)
        ptr[(size_t)(ty * 32 + r) * NPOS + n] = tf32r(t[r] * inv);
}

// ---------------- kmean: warp per channel ----------------
__global__ void kmean_k(const float* __restrict__ kbase, float* __restrict__ km)
{
    int b = blockIdx.y;
    int wid = threadIdx.x >> 5, lane = threadIdx.x & 31;
    int d = blockIdx.x * 8 + wid;
    const float4* kp = (const float4*)(kbase + (size_t)b * QKVD * NPOS + (size_t)d * NPOS);
    float s = 0.f;
#pragma unroll 8
    for (int i = lane; i < NPOS / 4; i += 32) {
        float4 v = kp[i];
        s += (v.x + v.y) + (v.z + v.w);
    }
#pragma unroll
    for (int o = 16; o > 0; o >>= 1) s += __shfl_xor_sync(0xFFFFFFFFu, s, o);
    if (lane == 0) km[b * DIM + d] = s * (1.f / (float)NPOS);
}

// ---------------- z[b][n] = kmean · q[:, n] + eps  (q in [d][n]) ----------------
__global__ void zcalc(const float* __restrict__ q, const float* __restrict__ km, float* __restrict__ zo)
{
    __shared__ float kms[256];
    int b = blockIdx.y;
    int tid = threadIdx.x;
    kms[tid] = km[b * DIM + tid];
    __syncthreads();
    int n = blockIdx.x * 256 + tid;
    const float* qp = q + (size_t)b * QKVD * NPOS + n;
    float s = 0.f;
#pragma unroll 4
    for (int d = 0; d < 256; ++d) s += kms[d] * qp[(size_t)d * NPOS];
    zo[(size_t)b * NPOS + n] = s + EPSF;
}

// ---------------- vkt reduce (8 chunks) + 1/N, tf32-rounded ----------------
__global__ void vkt_reduce(const float* __restrict__ part, float* __restrict__ vkT)
{
    int idx = blockIdx.x * 256 + threadIdx.x;
    int b = idx >> 16, ij = idx & 65535;
    float s = 0.f;
#pragma unroll
    for (int c = 0; c < 8; ++c) s += part[(size_t)(b * 8 + c) * 65536 + ij];
    vkT[idx] = tf32r(s * (1.f / (float)NPOS));
}

// ---------------- depthwise 5x5 on v slice -> dw ----------------
__global__ void dwconv_kernel(const float* __restrict__ vbase, const float* __restrict__ w,
                              const float* __restrict__ bias, float* __restrict__ dw)
{
    int ch = blockIdx.x, b = blockIdx.y;
    const float* vp = vbase + (size_t)b * QKVD * NPOS + (size_t)ch * NPOS;
    __shared__ float sm[68][68];
    __shared__ float ws[25];
    int tid = threadIdx.x;
    if (tid < 25) ws[tid] = w[ch * 25 + tid];
    for (int idx = tid; idx < 68 * 68; idx += 256) {
        int r = idx / 68, c = idx % 68;
        int gr = r - 2, gc = c - 2;
        sm[r][c] = (gr >= 0 && gr < HH && gc >= 0 && gc < WW) ? vp[gr * WW + gc] : 0.f;
    }
    __syncthreads();
    float bv = bias[ch];
    for (int p = tid; p < NPOS; p += 256) {
        int py = p >> 6, px = p & 63;
        float acc = bv;
#pragma unroll
        for (int ky = 0; ky < 5; ++ky)
#pragma unroll
            for (int kx = 0; kx < 5; ++kx)
                acc += sm[py + ky][px + kx] * ws[ky * 5 + kx];
        dw[((size_t)b * DIM + ch) * NPOS + p] = acc;
    }
}

// ---------------- host ----------------
extern "C" void kernel_launch(void* const* d_in, const int* in_sizes, int n_in,
                              void* d_out, int out_size)
{
    const float* x      = (const float*)d_in[0];
    const float* qkv_w  = (const float*)d_in[1];
    const float* qkv_b  = (const float*)d_in[2];
    const float* dwc_w  = (const float*)d_in[3];
    const float* dwc_b  = (const float*)d_in[4];
    const float* norm_w = (const float*)d_in[5];
    const float* proj_w = (const float*)d_in[6];
    const float* proj_b = (const float*)d_in[7];
    float* out = (float*)d_out;

    float *p_x, *p_qkv, *p_vkT, *p_part, *p_dw, *p_y, *p_z, *p_km, *p_qw, *p_pw;
    cudaGetSymbolAddress((void**)&p_x, g_x);
    cudaGetSymbolAddress((void**)&p_qkv, g_qkv);
    cudaGetSymbolAddress((void**)&p_vkT, g_vkT);
    cudaGetSymbolAddress((void**)&p_part, g_part);
    cudaGetSymbolAddress((void**)&p_dw, g_dw);
    cudaGetSymbolAddress((void**)&p_y, g_y);
    cudaGetSymbolAddress((void**)&p_z, g_z);
    cudaGetSymbolAddress((void**)&p_km, g_kmean);
    cudaGetSymbolAddress((void**)&p_qw, g_qw);
    cudaGetSymbolAddress((void**)&p_pw, g_pw);

    const float* p_k = p_qkv;   // slices
    const size_t kOff = (size_t)256 * NPOS, vOff = (size_t)512 * NPOS;

    const int SMEM_G = 6 * STG_W * 4;                              // 61440
    const int SMEM_A = (EPI_W + 256 + 4 * 132 + 128) * 4;          // ~90.4 KB
    cudaFuncSetAttribute(mma_gemm, cudaFuncAttributeMaxDynamicSharedMemorySize, SMEM_G);
    cudaFuncSetAttribute(attn_fused, cudaFuncAttributeMaxDynamicSharedMemorySize, SMEM_A);

    // 1-3. round x and weights to tf32
    round_copy<<<(BATCH * DIM * NPOS + 255) / 256, 256>>>(x, p_x, BATCH * DIM * NPOS);
    round_copy<<<(QKVD * DIM + 255) / 256, 256>>>(qkv_w, p_qw, QKVD * DIM);
    round_copy<<<(DIM * DIM + 255) / 256, 256>>>(proj_w, p_pw, DIM * DIM);
    // 4. qkv[768][n] = qkv_w · x  (B = x transposed-on-load), bias per-row, rounded
    mma_gemm<<<dim3(NPOS / 128, QKVD / 128, BATCH), 256, SMEM_G>>>(
        p_qw, p_x, qkv_b, p_qkv, 256, DIM, NPOS, NPOS,
        0LL, (long long)DIM * NPOS, (long long)QKVD * NPOS, 1, 2, 1, 1);
    // 5. featmap q,k in place
    featmap_kernel<<<dim3(NPOS / 32, 2, BATCH), dim3(32, 8)>>>(p_qkv);
    // 6,7. kmean, z
    kmean_k<<<dim3(DIM / 8, BATCH), 256>>>(p_qkv + kOff, p_km);
    zcalc<<<dim3(NPOS / 256, BATCH), 256>>>(p_qkv, p_km, p_z);
    // 8,9. vkT = v · k^T / N  (split-K x8)
    mma_gemm<<<dim3(2, 2, BATCH * 8), 256, SMEM_G>>>(
        p_qkv + vOff, p_k + kOff, nullptr, p_part, 512, NPOS, NPOS, DIM,
        (long long)QKVD * NPOS, (long long)QKVD * NPOS, (long long)DIM * DIM, 8, 0, 0, 0);
    vkt_reduce<<<dim3(BATCH * DIM * DIM / 256), 256>>>(p_part, p_vkT);
    // 10. depthwise conv on v
    dwconv_kernel<<<dim3(DIM, BATCH), 256>>>(p_qkv + vOff, dwc_w, dwc_b, p_dw);
    // 11. fused attn -> y[d][n]
    attn_fused<<<dim3(NPOS / 128, 1, BATCH), 512, SMEM_A>>>(p_vkT, p_qkv, p_z, p_dw, norm_w, p_y);
    // 12. out[c][n] = proj_w · y + proj_b  (B = y transposed-on-load)
    mma_gemm<<<dim3(NPOS / 128, DIM / 128, BATCH), 256, SMEM_G>>>(
        p_pw, p_y, proj_b, out, 256, DIM, NPOS, NPOS,
        0LL, (long long)DIM * NPOS, (long long)DIM * NPOS, 1, 2, 1, 0);
}

// round 10
// speedup vs baseline: 4.6422x; 1.0444x over previous
#include <cuda_runtime.h>
#include <cstdint>

#define BATCH 16
#define DIM   256
#define NPOS  4096
#define QKVD  768
#define HH    64
#define WW    64
#define EPSF  1e-5f

// ---------------- scratch ----------------
__device__ float g_x  [(size_t)BATCH * DIM * NPOS];    // tf32-rounded x [b][c][n]
__device__ float g_qkv[(size_t)BATCH * QKVD * NPOS];   // [b][768][n]: q 0-255, k 256-511, v 512-767
__device__ float g_vkT[(size_t)BATCH * DIM * DIM];
__device__ float g_part[(size_t)BATCH * 8 * DIM * DIM];
__device__ float g_dw [(size_t)BATCH * DIM * NPOS];    // [b][d][n]
__device__ float g_y  [(size_t)BATCH * DIM * NPOS];    // [b][d][n]
__device__ float g_z  [(size_t)BATCH * NPOS];
__device__ float g_kmean[BATCH * DIM];
__device__ float g_qw[QKVD * DIM];
__device__ float g_pw[DIM * DIM];

__device__ __forceinline__ uint32_t f2tf32(float v) {
    uint32_t u;
    asm("cvt.rn.tf32.f32 %0, %1;" : "=r"(u) : "f"(v));
    return u;
}
__device__ __forceinline__ float tf32r(float v) { return __uint_as_float(f2tf32(v)); }

__device__ __forceinline__ void cp16(uint32_t smem, const float* g) {
    asm volatile("cp.async.cg.shared.global [%0], [%1], 16;" :: "r"(smem), "l"(g));
}
#define CP_COMMIT() asm volatile("cp.async.commit_group;" ::: "memory")
#define CP_WAIT1()  asm volatile("cp.async.wait_group 1;" ::: "memory")

__device__ __forceinline__ void ldsm_x4(uint32_t& r0, uint32_t& r1, uint32_t& r2, uint32_t& r3,
                                        uint32_t addr) {
    asm volatile("ldmatrix.sync.aligned.m8n8.x4.shared.b16 {%0,%1,%2,%3}, [%4];"
                 : "=r"(r0), "=r"(r1), "=r"(r2), "=r"(r3) : "r"(addr));
}

#define MMA_TF32(acc, a0, a1, a2, a3, b0, b1) \
    asm volatile("mma.sync.aligned.m16n8k8.row.col.f32.tf32.tf32.f32 " \
                 "{%0,%1,%2,%3}, {%4,%5,%6,%7}, {%8,%9}, {%0,%1,%2,%3};" \
                 : "+f"((acc)[0]), "+f"((acc)[1]), "+f"((acc)[2]), "+f"((acc)[3]) \
                 : "r"(a0), "r"(a1), "r"(a2), "r"(a3), "r"(b0), "r"(b1))

// A-fragment LDSM lane offset: rows 0-7/8-15 x k-halves 0/4  (stride 20 words)
__device__ __forceinline__ uint32_t ldsmA_off(int lane) {
    int row = ((lane >> 3) & 1) * 8 + (lane & 7);
    int col = (lane >> 4) * 4;
    return (uint32_t)(row * 20 + col) * 4;
}
// B-fragment LDSM lane offset: n-blocks 0/8 x k-halves 0/4 (stride 20 words)
__device__ __forceinline__ uint32_t ldsmB_off(int lane) {
    int row = (lane >> 4) * 8 + (lane & 7);
    int col = ((lane >> 3) & 1) * 4;
    return (uint32_t)(row * 20 + col) * 4;
}

// ---------------- tf32 mma.sync GEMM, cp.async 3-stage: C[128m x 128n] = A[m,K]·Bop ----------------
// A row-major K-contiguous, pre-rounded tf32. If bTrans==0: B row-major [n][K]. If bTrans==1:
// B is [K][Ntotal] (n-contiguous), transposed on load. 256 threads.
#define STG_W 2560
__global__ __launch_bounds__(256)
void mma_gemm(const float* __restrict__ A, const float* __restrict__ B,
              const float* __restrict__ bias, float* __restrict__ C,
              int K, int ldA, int ldB, int ldC,
              long long aStride, long long bStride, long long cStride,
              int kChunks, int biasMode, int bTrans, int roundC)
{
    extern __shared__ float sm[];

    int z = blockIdx.z;
    int b = z / kChunks, chunk = z - b * kChunks;
    int kStart = chunk * K;
    int m0 = blockIdx.y * 128, n0 = blockIdx.x * 128;
    const float* Ab = A + (size_t)b * aStride + (size_t)m0 * ldA + kStart;
    float* Cb = C + (size_t)z * cStride;

    int tid = threadIdx.x;
    int lane = tid & 31, wid = tid >> 5;
    int g = lane >> 2, tig = lane & 3;
    int warp_m = (wid & 1) * 64, warp_n = (wid >> 1) * 32;

    uint32_t sbase;
    asm("{ .reg .u64 t; cvta.to.shared.u64 t, %1; cvt.u32.u64 %0, t; }" : "=r"(sbase) : "l"(sm));
    const uint32_t STG_B = STG_W * 4;
    uint32_t sA = sbase, sB = sbase + 3 * STG_B;

    // loaders
    int lr0 = tid >> 2;
    int lko = (tid & 3) * 4;
    uint32_t aoff0 = (uint32_t)(lr0 * 20 + lko) * 4;
    uint32_t aoff1 = (uint32_t)((lr0 + 64) * 20 + lko) * 4;
    const float* ag0 = Ab + (size_t)lr0 * ldA + lko;
    const float* ag1 = Ab + (size_t)(lr0 + 64) * ldA + lko;

    const float* bg0 = nullptr; const float* bg1 = nullptr;
    uint32_t boff0 = 0, boff1 = 0;
    const float* btg = nullptr;
    int tkr0 = 0, tkr1 = 0, tco0 = 0, tco1 = 0;
    uint32_t toff0 = 0, toff1 = 0;
    if (!bTrans) {
        const float* Bb = B + (size_t)b * bStride + (size_t)n0 * ldB + kStart;
        bg0 = Bb + (size_t)lr0 * ldB + lko;
        bg1 = Bb + (size_t)(lr0 + 64) * ldB + lko;
        boff0 = aoff0; boff1 = aoff1;
    } else {
        btg = B + (size_t)b * bStride + (size_t)kStart * ldB + n0;
        int c0 = tid, c1 = tid + 256;
        tkr0 = c0 >> 5; tco0 = (c0 & 31) * 4;
        tkr1 = c1 >> 5; tco1 = (c1 & 31) * 4;
        toff0 = (uint32_t)(tkr0 * 132 + tco0) * 4;
        toff1 = (uint32_t)(tkr1 * 132 + tco1) * 4;
    }

    uint32_t aF = ldsmA_off(lane) + (uint32_t)warp_m * 80;   // + stage + i*16*80 + kb*4
    uint32_t bF = ldsmB_off(lane) + (uint32_t)warp_n * 80;

    int S = K >> 4;

    float acc[4][4][4];
#pragma unroll
    for (int i = 0; i < 4; ++i)
#pragma unroll
        for (int j = 0; j < 4; ++j)
#pragma unroll
            for (int r = 0; r < 4; ++r) acc[i][j][r] = 0.f;

#pragma unroll
    for (int ps = 0; ps < 2; ++ps) {
        int kc = ps * 16;
        uint32_t so = ps * STG_B;
        cp16(sA + so + aoff0, ag0 + kc);
        cp16(sA + so + aoff1, ag1 + kc);
        if (!bTrans) {
            cp16(sB + so + boff0, bg0 + kc);
            cp16(sB + so + boff1, bg1 + kc);
        } else {
            cp16(sB + so + toff0, btg + (size_t)(kc + tkr0) * ldB + tco0);
            cp16(sB + so + toff1, btg + (size_t)(kc + tkr1) * ldB + tco1);
        }
        CP_COMMIT();
    }

    for (int s = 0; s < S; ++s) {
        CP_WAIT1();
        __syncthreads();
        if (s + 2 < S) {
            int buf2 = (s + 2) % 3;
            int kc = (s + 2) * 16;
            uint32_t so = buf2 * STG_B;
            cp16(sA + so + aoff0, ag0 + kc);
            cp16(sA + so + aoff1, ag1 + kc);
            if (!bTrans) {
                cp16(sB + so + boff0, bg0 + kc);
                cp16(sB + so + boff1, bg1 + kc);
            } else {
                cp16(sB + so + toff0, btg + (size_t)(kc + tkr0) * ldB + tco0);
                cp16(sB + so + toff1, btg + (size_t)(kc + tkr1) * ldB + tco1);
            }
        }
        CP_COMMIT();
        uint32_t stA = sA + (s % 3) * STG_B;
        uint32_t stB = sB + (s % 3) * STG_B;
        const float* Bs_ = sm + 3 * STG_W + (s % 3) * STG_W;
#pragma unroll
        for (int kb = 0; kb < 16; kb += 8) {
            uint32_t af[4][4], bf[4][2];
#pragma unroll
            for (int i = 0; i < 4; ++i)
                ldsm_x4(af[i][0], af[i][1], af[i][2], af[i][3],
                        stA + aF + (uint32_t)(i * 16 * 80 + kb * 4));
            if (!bTrans) {
#pragma unroll
                for (int jj = 0; jj < 2; ++jj)
                    ldsm_x4(bf[jj * 2][0], bf[jj * 2][1], bf[jj * 2 + 1][0], bf[jj * 2 + 1][1],
                            stB + bF + (uint32_t)(jj * 16 * 80 + kb * 4));
            } else {
#pragma unroll
                for (int j = 0; j < 4; ++j) {
                    int c0 = warp_n + j * 8 + g;
                    bf[j][0] = __float_as_uint(Bs_[(kb + tig) * 132 + c0]);
                    bf[j][1] = __float_as_uint(Bs_[(kb + tig + 4) * 132 + c0]);
                }
            }
#pragma unroll
            for (int i = 0; i < 4; ++i)
#pragma unroll
                for (int j = 0; j < 4; ++j)
                    MMA_TF32(acc[i][j], af[i][0], af[i][1], af[i][2], af[i][3], bf[j][0], bf[j][1]);
        }
    }

    // epilogue
#pragma unroll
    for (int i = 0; i < 4; ++i) {
        int row0 = m0 + warp_m + i * 16 + g;
        float br0 = (biasMode == 2) ? bias[row0] : 0.f;
        float br1 = (biasMode == 2) ? bias[row0 + 8] : 0.f;
#pragma unroll
        for (int j = 0; j < 4; ++j) {
            int col = n0 + warp_n + j * 8 + tig * 2;
            float2 v0 = make_float2(acc[i][j][0] + br0, acc[i][j][1] + br0);
            float2 v1 = make_float2(acc[i][j][2] + br1, acc[i][j][3] + br1);
            if (roundC) {
                v0.x = tf32r(v0.x); v0.y = tf32r(v0.y);
                v1.x = tf32r(v1.x); v1.y = tf32r(v1.y);
            }
            *(float2*)&Cb[(size_t)row0 * ldC + col] = v0;
            *(float2*)&Cb[(size_t)(row0 + 8) * ldC + col] = v1;
        }
    }
}

// ---------------- fused attn: y[d][n] = RMSNorm((vkT·q)/z)*nw + dw.  M=256, 512 threads ----------------
#define A_STG 5120   // 256 rows * 20 words
#define B_STG 2112   // 16 k-rows * 132 words
#define EPI_W (3 * A_STG + 3 * B_STG)
__global__ __launch_bounds__(512)
void attn_fused(const float* __restrict__ vkT, const float* __restrict__ q,
                const float* __restrict__ zbuf, const float* __restrict__ dw,
                const float* __restrict__ norm_w, float* __restrict__ y)
{
    extern __shared__ float sm[];
    float* nw  = sm + EPI_W;
    float* ssq = nw + 256;
    float* rr  = ssq + 4 * 132;

    int b = blockIdx.z;
    int n0 = blockIdx.x * 128;
    const float* Ab = vkT + (size_t)b * DIM * DIM;
    const float* qg = q + (size_t)b * QKVD * NPOS + n0;
    const float* dp = dw + (size_t)b * DIM * NPOS;
    float* yp = y + (size_t)b * DIM * NPOS;

    int tid = threadIdx.x;
    int lane = tid & 31, wid = tid >> 5;
    int g = lane >> 2, tig = lane & 3;
    int warp_m = (wid & 3) * 64, warp_n = (wid >> 2) * 32;

    if (tid < 256) nw[tid] = norm_w[tid];

    uint32_t sbase;
    asm("{ .reg .u64 t; cvta.to.shared.u64 t, %1; cvt.u32.u64 %0, t; }" : "=r"(sbase) : "l"(sm));
    uint32_t sA = sbase, sB = sbase + 3 * A_STG * 4;

    int ac0 = tid, ac1 = tid + 512;
    int ar0 = ac0 >> 2, ako0 = (ac0 & 3) * 4;
    int ar1 = ac1 >> 2, ako1 = (ac1 & 3) * 4;
    uint32_t aoff0 = (uint32_t)(ar0 * 20 + ako0) * 4;
    uint32_t aoff1 = (uint32_t)(ar1 * 20 + ako1) * 4;
    int bkr = tid >> 5, bco = (tid & 31) * 4;
    uint32_t boff = (uint32_t)(bkr * 132 + bco) * 4;

    uint32_t aF = ldsmA_off(lane) + (uint32_t)warp_m * 80;

#pragma unroll
    for (int ps = 0; ps < 2; ++ps) {
        int kc = ps * 16;
        cp16(sA + ps * A_STG * 4 + aoff0, Ab + (size_t)ar0 * DIM + kc + ako0);
        cp16(sA + ps * A_STG * 4 + aoff1, Ab + (size_t)ar1 * DIM + kc + ako1);
        cp16(sB + ps * B_STG * 4 + boff, qg + (size_t)(kc + bkr) * NPOS + bco);
        CP_COMMIT();
    }

    float acc[4][4][4];
#pragma unroll
    for (int i = 0; i < 4; ++i)
#pragma unroll
        for (int j = 0; j < 4; ++j)
#pragma unroll
            for (int r = 0; r < 4; ++r) acc[i][j][r] = 0.f;

    const int S = 16;
    for (int s = 0; s < S; ++s) {
        CP_WAIT1();
        __syncthreads();
        if (s + 2 < S) {
            int buf2 = (s + 2) % 3;
            int kc = (s + 2) * 16;
            cp16(sA + buf2 * A_STG * 4 + aoff0, Ab + (size_t)ar0 * DIM + kc + ako0);
            cp16(sA + buf2 * A_STG * 4 + aoff1, Ab + (size_t)ar1 * DIM + kc + ako1);
            cp16(sB + buf2 * B_STG * 4 + boff, qg + (size_t)(kc + bkr) * NPOS + bco);
        }
        CP_COMMIT();
        uint32_t stA = sA + (s % 3) * A_STG * 4;
        const float* Bs_ = sm + 3 * A_STG + (s % 3) * B_STG;
#pragma unroll
        for (int kb = 0; kb < 16; kb += 8) {
            uint32_t af[4][4], bf[4][2];
#pragma unroll
            for (int i = 0; i < 4; ++i)
                ldsm_x4(af[i][0], af[i][1], af[i][2], af[i][3],
                        stA + aF + (uint32_t)(i * 16 * 80 + kb * 4));
#pragma unroll
            for (int j = 0; j < 4; ++j) {
                int c0 = warp_n + j * 8 + g;
                bf[j][0] = __float_as_uint(Bs_[(kb + tig) * 132 + c0]);
                bf[j][1] = __float_as_uint(Bs_[(kb + tig + 4) * 132 + c0]);
            }
#pragma unroll
            for (int i = 0; i < 4; ++i)
#pragma unroll
                for (int j = 0; j < 4; ++j)
                    MMA_TF32(acc[i][j], af[i][0], af[i][1], af[i][2], af[i][3], bf[j][0], bf[j][1]);
        }
    }

    // ---- fused epilogue ----
    float ss[8];
#pragma unroll
    for (int j = 0; j < 4; ++j) {
        int col = warp_n + j * 8 + tig * 2;
        float2 zv = *(const float2*)&zbuf[(size_t)b * NPOS + n0 + col];
        float iz0 = 1.f / zv.x, iz1 = 1.f / zv.y;
        float s0 = 0.f, s1 = 0.f;
#pragma unroll
        for (int i = 0; i < 4; ++i) {
            acc[i][j][0] *= iz0; acc[i][j][1] *= iz1;
            acc[i][j][2] *= iz0; acc[i][j][3] *= iz1;
            s0 += acc[i][j][0] * acc[i][j][0] + acc[i][j][2] * acc[i][j][2];
            s1 += acc[i][j][1] * acc[i][j][1] + acc[i][j][3] * acc[i][j][3];
        }
        ss[j * 2] = s0; ss[j * 2 + 1] = s1;
    }
#pragma unroll
    for (int o = 4; o <= 16; o <<= 1)
#pragma unroll
        for (int c = 0; c < 8; ++c) ss[c] += __shfl_xor_sync(0xFFFFFFFFu, ss[c], o);
    __syncthreads();
    if (g == 0) {
        int wm = wid & 3;
#pragma unroll
        for (int j = 0; j < 4; ++j) {
            int col = warp_n + j * 8 + tig * 2;
            ssq[wm * 132 + col] = ss[j * 2];
            ssq[wm * 132 + col + 1] = ss[j * 2 + 1];
        }
    }
    __syncthreads();
    if (tid < 128) {
        float s = ssq[tid] + ssq[132 + tid] + ssq[264 + tid] + ssq[396 + tid];
        rr[tid] = rsqrtf(s * (1.f / (float)DIM) + EPSF);
    }
    __syncthreads();
#pragma unroll
    for (int i = 0; i < 4; ++i) {
        int row0 = warp_m + i * 16 + g;
#pragma unroll
        for (int j = 0; j < 4; ++j) {
            int col = warp_n + j * 8 + tig * 2;
            float r0 = rr[col], r1 = rr[col + 1];
            float2 d0 = *(const float2*)&dp[(size_t)row0 * NPOS + n0 + col];
            float2 d1 = *(const float2*)&dp[(size_t)(row0 + 8) * NPOS + n0 + col];
            float2 v0, v1;
            v0.x = tf32r(acc[i][j][0] * r0 * nw[row0] + d0.x);
            v0.y = tf32r(acc[i][j][1] * r1 * nw[row0] + d0.y);
            v1.x = tf32r(acc[i][j][2] * r0 * nw[row0 + 8] + d1.x);
            v1.y = tf32r(acc[i][j][3] * r1 * nw[row0 + 8] + d1.y);
            *(float2*)&yp[(size_t)row0 * NPOS + n0 + col] = v0;
            *(float2*)&yp[(size_t)(row0 + 8) * NPOS + n0 + col] = v1;
        }
    }
}

// ---------------- round-copy to tf32 ----------------
__global__ void round_copy(const float* __restrict__ in, float* __restrict__ out, int n)
{
    int i = blockIdx.x * 256 + threadIdx.x;
    if (i < n) out[i] = tf32r(in[i]);
}

// ---------------- featmap in place on [d][n] slice ----------------
__global__ void featmap_kernel(float* __restrict__ qkv)
{
    int b = blockIdx.z;
    float* ptr = qkv + ((size_t)b * QKVD + (blockIdx.y ? 256 : 0)) * NPOS;
    int tx = threadIdx.x, ty = threadIdx.y;          // 32 x 8
    int n = blockIdx.x * 32 + tx;
    float t[32];
    float s = 0.f;
#pragma unroll
    for (int r = 0; r < 32; ++r) {
        float v = ptr[(size_t)(ty * 32 + r) * NPOS + n];
        v = fmaxf(v, 0.f) + EPSF;
        v = v * v;
        t[r] = v;
        s += v * v;
    }
    __shared__ float red[8][33];
    __shared__ float nrm[32];
    red[ty][tx] = s;
    __syncthreads();
    if (ty == 0) {
        float tot = 0.f;
#pragma unroll
        for (int k = 0; k < 8; ++k) tot += red[k][tx];
        nrm[tx] = 1.f / fmaxf(sqrtf(tot), 1e-12f);
    }
    __syncthreads();
    float inv = nrm[tx];
#pragma unroll
    for (int r = 0; r < 32; ++r)
        ptr[(size_t)(ty * 32 + r) * NPOS + n] = tf32r(t[r] * inv);
}

// ---------------- kmean: warp per channel ----------------
__global__ void kmean_k(const float* __restrict__ kbase, float* __restrict__ km)
{
    int b = blockIdx.y;
    int wid = threadIdx.x >> 5, lane = threadIdx.x & 31;
    int d = blockIdx.x * 8 + wid;
    const float4* kp = (const float4*)(kbase + (size_t)b * QKVD * NPOS + (size_t)d * NPOS);
    float s = 0.f;
#pragma unroll 8
    for (int i = lane; i < NPOS / 4; i += 32) {
        float4 v = kp[i];
        s += (v.x + v.y) + (v.z + v.w);
    }
#pragma unroll
    for (int o = 16; o > 0; o >>= 1) s += __shfl_xor_sync(0xFFFFFFFFu, s, o);
    if (lane == 0) km[b * DIM + d] = s * (1.f / (float)NPOS);
}

// ---------------- z[b][n] = kmean · q[:, n] + eps ----------------
__global__ void zcalc(const float* __restrict__ q, const float* __restrict__ km, float* __restrict__ zo)
{
    __shared__ float kms[256];
    int b = blockIdx.y;
    int tid = threadIdx.x;
    kms[tid] = km[b * DIM + tid];
    __syncthreads();
    int n = blockIdx.x * 256 + tid;
    const float* qp = q + (size_t)b * QKVD * NPOS + n;
    float s = 0.f;
#pragma unroll 4
    for (int d = 0; d < 256; ++d) s += kms[d] * qp[(size_t)d * NPOS];
    zo[(size_t)b * NPOS + n] = s + EPSF;
}

// ---------------- vkt reduce (8 chunks) + 1/N, tf32-rounded ----------------
__global__ void vkt_reduce(const float* __restrict__ part, float* __restrict__ vkT)
{
    int idx = blockIdx.x * 256 + threadIdx.x;
    int b = idx >> 16, ij = idx & 65535;
    float s = 0.f;
#pragma unroll
    for (int c = 0; c < 8; ++c) s += part[(size_t)(b * 8 + c) * 65536 + ij];
    vkT[idx] = tf32r(s * (1.f / (float)NPOS));
}

// ---------------- depthwise 5x5 on v slice -> dw ----------------
__global__ void dwconv_kernel(const float* __restrict__ vbase, const float* __restrict__ w,
                              const float* __restrict__ bias, float* __restrict__ dw)
{
    int ch = blockIdx.x, b = blockIdx.y;
    const float* vp = vbase + (size_t)b * QKVD * NPOS + (size_t)ch * NPOS;
    __shared__ float sm[68][68];
    __shared__ float ws[25];
    int tid = threadIdx.x;
    if (tid < 25) ws[tid] = w[ch * 25 + tid];
    for (int idx = tid; idx < 68 * 68; idx += 256) {
        int r = idx / 68, c = idx % 68;
        int gr = r - 2, gc = c - 2;
        sm[r][c] = (gr >= 0 && gr < HH && gc >= 0 && gc < WW) ? vp[gr * WW + gc] : 0.f;
    }
    __syncthreads();
    float bv = bias[ch];
    for (int p = tid; p < NPOS; p += 256) {
        int py = p >> 6, px = p & 63;
        float acc = bv;
#pragma unroll
        for (int ky = 0; ky < 5; ++ky)
#pragma unroll
            for (int kx = 0; kx < 5; ++kx)
                acc += sm[py + ky][px + kx] * ws[ky * 5 + kx];
        dw[((size_t)b * DIM + ch) * NPOS + p] = acc;
    }
}

// ---------------- host ----------------
extern "C" void kernel_launch(void* const* d_in, const int* in_sizes, int n_in,
                              void* d_out, int out_size)
{
    const float* x      = (const float*)d_in[0];
    const float* qkv_w  = (const float*)d_in[1];
    const float* qkv_b  = (const float*)d_in[2];
    const float* dwc_w  = (const float*)d_in[3];
    const float* dwc_b  = (const float*)d_in[4];
    const float* norm_w = (const float*)d_in[5];
    const float* proj_w = (const float*)d_in[6];
    const float* proj_b = (const float*)d_in[7];
    float* out = (float*)d_out;

    float *p_x, *p_qkv, *p_vkT, *p_part, *p_dw, *p_y, *p_z, *p_km, *p_qw, *p_pw;
    cudaGetSymbolAddress((void**)&p_x, g_x);
    cudaGetSymbolAddress((void**)&p_qkv, g_qkv);
    cudaGetSymbolAddress((void**)&p_vkT, g_vkT);
    cudaGetSymbolAddress((void**)&p_part, g_part);
    cudaGetSymbolAddress((void**)&p_dw, g_dw);
    cudaGetSymbolAddress((void**)&p_y, g_y);
    cudaGetSymbolAddress((void**)&p_z, g_z);
    cudaGetSymbolAddress((void**)&p_km, g_kmean);
    cudaGetSymbolAddress((void**)&p_qw, g_qw);
    cudaGetSymbolAddress((void**)&p_pw, g_pw);

    const float* p_k = p_qkv;
    const size_t kOff = (size_t)256 * NPOS, vOff = (size_t)512 * NPOS;

    const int SMEM_G = 6 * STG_W * 4;
    const int SMEM_A = (EPI_W + 256 + 4 * 132 + 128) * 4;
    cudaFuncSetAttribute(mma_gemm, cudaFuncAttributeMaxDynamicSharedMemorySize, SMEM_G);
    cudaFuncSetAttribute(attn_fused, cudaFuncAttributeMaxDynamicSharedMemorySize, SMEM_A);

    // 1-3. round x and weights to tf32
    round_copy<<<(BATCH * DIM * NPOS + 255) / 256, 256>>>(x, p_x, BATCH * DIM * NPOS);
    round_copy<<<(QKVD * DIM + 255) / 256, 256>>>(qkv_w, p_qw, QKVD * DIM);
    round_copy<<<(DIM * DIM + 255) / 256, 256>>>(proj_w, p_pw, DIM * DIM);
    // 4. qkv[768][n] = qkv_w · x  (B trans-on-load), bias per-row, rounded
    mma_gemm<<<dim3(NPOS / 128, QKVD / 128, BATCH), 256, SMEM_G>>>(
        p_qw, p_x, qkv_b, p_qkv, 256, DIM, NPOS, NPOS,
        0LL, (long long)DIM * NPOS, (long long)QKVD * NPOS, 1, 2, 1, 1);
    // 5. featmap q,k in place
    featmap_kernel<<<dim3(NPOS / 32, 2, BATCH), dim3(32, 8)>>>(p_qkv);
    // 6,7. kmean, z
    kmean_k<<<dim3(DIM / 8, BATCH), 256>>>(p_qkv + kOff, p_km);
    zcalc<<<dim3(NPOS / 256, BATCH), 256>>>(p_qkv, p_km, p_z);
    // 8,9. vkT = v · k^T / N  (split-K x8)
    mma_gemm<<<dim3(2, 2, BATCH * 8), 256, SMEM_G>>>(
        p_qkv + vOff, p_k + kOff, nullptr, p_part, 512, NPOS, NPOS, DIM,
        (long long)QKVD * NPOS, (long long)QKVD * NPOS, (long long)DIM * DIM, 8, 0, 0, 0);
    vkt_reduce<<<dim3(BATCH * DIM * DIM / 256), 256>>>(p_part, p_vkT);
    // 10. depthwise conv on v
    dwconv_kernel<<<dim3(DIM, BATCH), 256>>>(p_qkv + vOff, dwc_w, dwc_b, p_dw);
    // 11. fused attn -> y[d][n]
    attn_fused<<<dim3(NPOS / 128, 1, BATCH), 512, SMEM_A>>>(p_vkT, p_qkv, p_z, p_dw, norm_w, p_y);
    // 12. out[c][n] = proj_w · y + proj_b  (B trans-on-load)
    mma_gemm<<<dim3(NPOS / 128, DIM / 128, BATCH), 256, SMEM_G>>>(
        p_pw, p_y, proj_b, out, 256, DIM, NPOS, NPOS,
        0LL, (long long)DIM * NPOS, (long long)DIM * NPOS, 1, 2, 1, 0);
}

// round 11
// speedup vs baseline: 6.7805x; 1.4606x over previous
#include <cuda_runtime.h>
#include <cuda_fp16.h>
#include <cstdint>

#define BATCH 16
#define DIM   256
#define NPOS  4096
#define QKVD  768
#define HH    64
#define WW    64
#define EPSF  1e-5f

// ---------------- scratch ----------------
__device__ __half g_xh [(size_t)BATCH * DIM * NPOS];    // fp16 x [b][c][n]
__device__ __half g_qkv[(size_t)BATCH * QKVD * NPOS];   // fp16 [b][768][n]
__device__ __half g_vkT[(size_t)BATCH * DIM * DIM];
__device__ float  g_part[(size_t)BATCH * 8 * DIM * DIM];
__device__ float  g_dw [(size_t)BATCH * DIM * NPOS];
__device__ __half g_y  [(size_t)BATCH * DIM * NPOS];
__device__ float  g_z  [(size_t)BATCH * NPOS];
__device__ float  g_kmean[BATCH * DIM];
__device__ __half g_qw[QKVD * DIM];
__device__ __half g_pw[DIM * DIM];

__device__ __forceinline__ void cp16(uint32_t smem, const void* g) {
    asm volatile("cp.async.cg.shared.global [%0], [%1], 16;" :: "r"(smem), "l"(g));
}
#define CP_COMMIT() asm volatile("cp.async.commit_group;" ::: "memory")
#define CP_WAIT1()  asm volatile("cp.async.wait_group 1;" ::: "memory")

__device__ __forceinline__ void ldsm_x4(uint32_t& r0, uint32_t& r1, uint32_t& r2, uint32_t& r3,
                                        uint32_t addr) {
    asm volatile("ldmatrix.sync.aligned.m8n8.x4.shared.b16 {%0,%1,%2,%3}, [%4];"
                 : "=r"(r0), "=r"(r1), "=r"(r2), "=r"(r3) : "r"(addr));
}
__device__ __forceinline__ void ldsm_x4_t(uint32_t& r0, uint32_t& r1, uint32_t& r2, uint32_t& r3,
                                          uint32_t addr) {
    asm volatile("ldmatrix.sync.aligned.m8n8.x4.trans.shared.b16 {%0,%1,%2,%3}, [%4];"
                 : "=r"(r0), "=r"(r1), "=r"(r2), "=r"(r3) : "r"(addr));
}

#define MMA_F16(acc, a0, a1, a2, a3, b0, b1) \
    asm volatile("mma.sync.aligned.m16n8k16.row.col.f32.f16.f16.f32 " \
                 "{%0,%1,%2,%3}, {%4,%5,%6,%7}, {%8,%9}, {%0,%1,%2,%3};" \
                 : "+f"((acc)[0]), "+f"((acc)[1]), "+f"((acc)[2]), "+f"((acc)[3]) \
                 : "r"(a0), "r"(a1), "r"(a2), "r"(a3), "r"(b0), "r"(b1))

// A-frag lane offset (48B row stride, [rows][k16])
__device__ __forceinline__ uint32_t ldsmA_off(int lane) {
    int row = ((lane >> 3) & 1) * 8 + (lane & 7);
    return (uint32_t)(row * 48 + (lane >> 4) * 16);
}
// B-frag (non-trans, [n][k16], 48B stride)
__device__ __forceinline__ uint32_t ldsmBn_off(int lane) {
    int row = ((lane >> 4) & 1) * 8 + (lane & 7);
    return (uint32_t)(row * 48 + ((lane >> 3) & 1) * 16);
}
// B-frag (trans, [k16][n], 272B stride)
__device__ __forceinline__ uint32_t ldsmBt_off(int lane) {
    int krow = ((lane >> 3) & 1) * 8 + (lane & 7);
    return (uint32_t)(krow * 272 + ((lane >> 4) & 1) * 16);
}

// ---------------- fp16 mma GEMM, cp.async 3-stage: C[128m x 128n] = A[m,K]·Bop ----------------
#define AST 6144   // stage bytes (128 rows * 48B)
__global__ __launch_bounds__(256)
void hgemm(const __half* __restrict__ A, const __half* __restrict__ B,
           const float* __restrict__ bias, void* __restrict__ Cv,
           int K, int ldA, int ldB, int ldC,
           long long aStride, long long bStride, long long cStride,
           int kChunks, int biasMode, int bTrans, int outHalf)
{
    extern __shared__ char smc[];

    int z = blockIdx.z;
    int b = z / kChunks, chunk = z - b * kChunks;
    int kStart = chunk * K;
    int m0 = blockIdx.y * 128, n0 = blockIdx.x * 128;
    const __half* Ab = A + (size_t)b * aStride + (size_t)m0 * ldA + kStart;

    int tid = threadIdx.x;
    int lane = tid & 31, wid = tid >> 5;
    int g = lane >> 2, tig = lane & 3;
    int warp_m = (wid & 1) * 64, warp_n = (wid >> 1) * 32;

    uint32_t sbase;
    asm("{ .reg .u64 t; cvta.to.shared.u64 t, %1; cvt.u32.u64 %0, t; }" : "=r"(sbase) : "l"(smc));
    uint32_t sA = sbase, sB = sbase + 3 * AST;

    // A loader: 256 chunks of 16B (8 halves)
    int arow = tid >> 1, akch = tid & 1;
    uint32_t aoff = (uint32_t)(arow * 48 + akch * 16);
    const __half* ag = Ab + (size_t)arow * ldA + akch * 8;

    // B loader
    const __half* bg = nullptr;
    const __half* btg = nullptr;
    uint32_t boff;
    int bkr = 0, bnc = 0;
    if (!bTrans) {
        const __half* Bb = B + (size_t)b * bStride + (size_t)n0 * ldB + kStart;
        bg = Bb + (size_t)arow * ldB + akch * 8;
        boff = aoff;
    } else {
        btg = B + (size_t)b * bStride + (size_t)kStart * ldB + n0;
        bkr = tid >> 4; bnc = tid & 15;
        boff = (uint32_t)(bkr * 272 + bnc * 16);
    }

    uint32_t aF = ldsmA_off(lane) + (uint32_t)warp_m * 48;
    uint32_t bFn = ldsmBn_off(lane) + (uint32_t)warp_n * 48;
    uint32_t bFt = ldsmBt_off(lane) + (uint32_t)warp_n * 2;

    int S = K >> 4;

    float acc[4][4][4];
#pragma unroll
    for (int i = 0; i < 4; ++i)
#pragma unroll
        for (int j = 0; j < 4; ++j)
#pragma unroll
            for (int r = 0; r < 4; ++r) acc[i][j][r] = 0.f;

#pragma unroll
    for (int ps = 0; ps < 2; ++ps) {
        int kc = ps * 16;
        uint32_t so = ps * AST;
        cp16(sA + so + aoff, ag + kc);
        if (!bTrans) cp16(sB + so + boff, bg + kc);
        else         cp16(sB + so + boff, btg + (size_t)(kc + bkr) * ldB + bnc * 8);
        CP_COMMIT();
    }

    for (int s = 0; s < S; ++s) {
        CP_WAIT1();
        __syncthreads();
        if (s + 2 < S) {
            int buf2 = (s + 2) % 3;
            int kc = (s + 2) * 16;
            uint32_t so = buf2 * AST;
            cp16(sA + so + aoff, ag + kc);
            if (!bTrans) cp16(sB + so + boff, bg + kc);
            else         cp16(sB + so + boff, btg + (size_t)(kc + bkr) * ldB + bnc * 8);
        }
        CP_COMMIT();
        uint32_t stA = sA + (s % 3) * AST;
        uint32_t stB = sB + (s % 3) * AST;
        uint32_t af[4][4], bf[4][2];
#pragma unroll
        for (int i = 0; i < 4; ++i)
            ldsm_x4(af[i][0], af[i][1], af[i][2], af[i][3], stA + aF + (uint32_t)(i * 16 * 48));
        if (!bTrans) {
#pragma unroll
            for (int jj = 0; jj < 2; ++jj)
                ldsm_x4(bf[2 * jj][0], bf[2 * jj][1], bf[2 * jj + 1][0], bf[2 * jj + 1][1],
                        stB + bFn + (uint32_t)(jj * 16 * 48));
        } else {
#pragma unroll
            for (int jj = 0; jj < 2; ++jj)
                ldsm_x4_t(bf[2 * jj][0], bf[2 * jj][1], bf[2 * jj + 1][0], bf[2 * jj + 1][1],
                          stB + bFt + (uint32_t)(jj * 32));
        }
#pragma unroll
        for (int i = 0; i < 4; ++i)
#pragma unroll
            for (int j = 0; j < 4; ++j)
                MMA_F16(acc[i][j], af[i][0], af[i][1], af[i][2], af[i][3], bf[j][0], bf[j][1]);
    }

    // epilogue
#pragma unroll
    for (int i = 0; i < 4; ++i) {
        int row0 = m0 + warp_m + i * 16 + g;
        float br0 = (biasMode == 2) ? bias[row0] : 0.f;
        float br1 = (biasMode == 2) ? bias[row0 + 8] : 0.f;
#pragma unroll
        for (int j = 0; j < 4; ++j) {
            int col = n0 + warp_n + j * 8 + tig * 2;
            if (outHalf) {
                __half* Ch = (__half*)Cv + (size_t)z * cStride;
                *(__half2*)&Ch[(size_t)row0 * ldC + col] =
                    __floats2half2_rn(acc[i][j][0] + br0, acc[i][j][1] + br0);
                *(__half2*)&Ch[(size_t)(row0 + 8) * ldC + col] =
                    __floats2half2_rn(acc[i][j][2] + br1, acc[i][j][3] + br1);
            } else {
                float* Cf = (float*)Cv + (size_t)z * cStride;
                *(float2*)&Cf[(size_t)row0 * ldC + col] =
                    make_float2(acc[i][j][0] + br0, acc[i][j][1] + br0);
                *(float2*)&Cf[(size_t)(row0 + 8) * ldC + col] =
                    make_float2(acc[i][j][2] + br1, acc[i][j][3] + br1);
            }
        }
    }
}

// ---------------- fused attn: y[d][n] = RMSNorm((vkT·q)/z)*nw + dw, fp16. 512 threads ----------------
#define AST2 12288   // 256 rows * 48B
#define BSTT 4352    // 16 k-rows * 272B
#define EPI_BYTES (3 * AST2 + 3 * BSTT)
__global__ __launch_bounds__(512)
void attn_fused(const __half* __restrict__ vkT, const __half* __restrict__ q,
                const float* __restrict__ zbuf, const float* __restrict__ dw,
                const float* __restrict__ norm_w, __half* __restrict__ y)
{
    extern __shared__ char smc[];
    float* nw  = (float*)(smc + EPI_BYTES);
    float* ssq = nw + 256;
    float* rr  = ssq + 4 * 132;

    int b = blockIdx.z;
    int n0 = blockIdx.x * 128;
    const __half* Ab = vkT + (size_t)b * DIM * DIM;
    const __half* qg = q + (size_t)b * QKVD * NPOS + n0;
    const float* dp = dw + (size_t)b * DIM * NPOS;
    __half* yp = y + (size_t)b * DIM * NPOS;

    int tid = threadIdx.x;
    int lane = tid & 31, wid = tid >> 5;
    int g = lane >> 2, tig = lane & 3;
    int warp_m = (wid & 3) * 64, warp_n = (wid >> 2) * 32;

    if (tid < 256) nw[tid] = norm_w[tid];

    uint32_t sbase;
    asm("{ .reg .u64 t; cvta.to.shared.u64 t, %1; cvt.u32.u64 %0, t; }" : "=r"(sbase) : "l"(smc));
    uint32_t sA = sbase, sB = sbase + 3 * AST2;

    int arow = tid >> 1, akch = tid & 1;
    uint32_t aoff = (uint32_t)(arow * 48 + akch * 16);
    int bkr = tid >> 4, bnc = tid & 15;
    uint32_t boff = (uint32_t)(bkr * 272 + bnc * 16);

    uint32_t aF = ldsmA_off(lane) + (uint32_t)warp_m * 48;
    uint32_t bFt = ldsmBt_off(lane) + (uint32_t)warp_n * 2;

#pragma unroll
    for (int ps = 0; ps < 2; ++ps) {
        int kc = ps * 16;
        cp16(sA + ps * AST2 + aoff, Ab + (size_t)arow * DIM + kc + akch * 8);
        if (tid < 256)
            cp16(sB + ps * BSTT + boff, qg + (size_t)(kc + bkr) * NPOS + bnc * 8);
        CP_COMMIT();
    }

    float acc[4][4][4];
#pragma unroll
    for (int i = 0; i < 4; ++i)
#pragma unroll
        for (int j = 0; j < 4; ++j)
#pragma unroll
            for (int r = 0; r < 4; ++r) acc[i][j][r] = 0.f;

    const int S = 16;
    for (int s = 0; s < S; ++s) {
        CP_WAIT1();
        __syncthreads();
        if (s + 2 < S) {
            int buf2 = (s + 2) % 3;
            int kc = (s + 2) * 16;
            cp16(sA + buf2 * AST2 + aoff, Ab + (size_t)arow * DIM + kc + akch * 8);
            if (tid < 256)
                cp16(sB + buf2 * BSTT + boff, qg + (size_t)(kc + bkr) * NPOS + bnc * 8);
        }
        CP_COMMIT();
        uint32_t stA = sA + (s % 3) * AST2;
        uint32_t stB = sB + (s % 3) * BSTT;
        uint32_t af[4][4], bf[4][2];
#pragma unroll
        for (int i = 0; i < 4; ++i)
            ldsm_x4(af[i][0], af[i][1], af[i][2], af[i][3], stA + aF + (uint32_t)(i * 16 * 48));
#pragma unroll
        for (int jj = 0; jj < 2; ++jj)
            ldsm_x4_t(bf[2 * jj][0], bf[2 * jj][1], bf[2 * jj + 1][0], bf[2 * jj + 1][1],
                      stB + bFt + (uint32_t)(jj * 32));
#pragma unroll
        for (int i = 0; i < 4; ++i)
#pragma unroll
            for (int j = 0; j < 4; ++j)
                MMA_F16(acc[i][j], af[i][0], af[i][1], af[i][2], af[i][3], bf[j][0], bf[j][1]);
    }

    // ---- fused epilogue ----
    float ss[8];
#pragma unroll
    for (int j = 0; j < 4; ++j) {
        int col = warp_n + j * 8 + tig * 2;
        float2 zv = *(const float2*)&zbuf[(size_t)b * NPOS + n0 + col];
        float iz0 = 1.f / zv.x, iz1 = 1.f / zv.y;
        float s0 = 0.f, s1 = 0.f;
#pragma unroll
        for (int i = 0; i < 4; ++i) {
            acc[i][j][0] *= iz0; acc[i][j][1] *= iz1;
            acc[i][j][2] *= iz0; acc[i][j][3] *= iz1;
            s0 += acc[i][j][0] * acc[i][j][0] + acc[i][j][2] * acc[i][j][2];
            s1 += acc[i][j][1] * acc[i][j][1] + acc[i][j][3] * acc[i][j][3];
        }
        ss[j * 2] = s0; ss[j * 2 + 1] = s1;
    }
#pragma unroll
    for (int o = 4; o <= 16; o <<= 1)
#pragma unroll
        for (int c = 0; c < 8; ++c) ss[c] += __shfl_xor_sync(0xFFFFFFFFu, ss[c], o);
    __syncthreads();
    if (g == 0) {
        int wm = wid & 3;
#pragma unroll
        for (int j = 0; j < 4; ++j) {
            int col = warp_n + j * 8 + tig * 2;
            ssq[wm * 132 + col] = ss[j * 2];
            ssq[wm * 132 + col + 1] = ss[j * 2 + 1];
        }
    }
    __syncthreads();
    if (tid < 128) {
        float s = ssq[tid] + ssq[132 + tid] + ssq[264 + tid] + ssq[396 + tid];
        rr[tid] = rsqrtf(s * (1.f / (float)DIM) + EPSF);
    }
    __syncthreads();
#pragma unroll
    for (int i = 0; i < 4; ++i) {
        int row0 = warp_m + i * 16 + g;
#pragma unroll
        for (int j = 0; j < 4; ++j) {
            int col = warp_n + j * 8 + tig * 2;
            float r0 = rr[col], r1 = rr[col + 1];
            float2 d0 = *(const float2*)&dp[(size_t)row0 * NPOS + n0 + col];
            float2 d1 = *(const float2*)&dp[(size_t)(row0 + 8) * NPOS + n0 + col];
            *(__half2*)&yp[(size_t)row0 * NPOS + n0 + col] =
                __floats2half2_rn(acc[i][j][0] * r0 * nw[row0] + d0.x,
                                  acc[i][j][1] * r1 * nw[row0] + d0.y);
            *(__half2*)&yp[(size_t)(row0 + 8) * NPOS + n0 + col] =
                __floats2half2_rn(acc[i][j][2] * r0 * nw[row0 + 8] + d1.x,
                                  acc[i][j][3] * r1 * nw[row0 + 8] + d1.y);
        }
    }
}

// ---------------- fp32 -> fp16 copy ----------------
__global__ void round_copy_h(const float* __restrict__ in, __half* __restrict__ out, int n)
{
    int i = blockIdx.x * 256 + threadIdx.x;
    if (i < n) out[i] = __float2half_rn(in[i]);
}

// ---------------- featmap in place on fp16 [d][n] slice ----------------
__global__ void featmap_kernel(__half* __restrict__ qkv)
{
    int b = blockIdx.z;
    __half* ptr = qkv + ((size_t)b * QKVD + (blockIdx.y ? 256 : 0)) * NPOS;
    int tx = threadIdx.x, ty = threadIdx.y;          // 32 x 8
    int n = blockIdx.x * 32 + tx;
    float t[32];
    float s = 0.f;
#pragma unroll
    for (int r = 0; r < 32; ++r) {
        float v = __half2float(ptr[(size_t)(ty * 32 + r) * NPOS + n]);
        v = fmaxf(v, 0.f) + EPSF;
        v = v * v;
        t[r] = v;
        s += v * v;
    }
    __shared__ float red[8][33];
    __shared__ float nrm[32];
    red[ty][tx] = s;
    __syncthreads();
    if (ty == 0) {
        float tot = 0.f;
#pragma unroll
        for (int k = 0; k < 8; ++k) tot += red[k][tx];
        nrm[tx] = 1.f / fmaxf(sqrtf(tot), 1e-12f);
    }
    __syncthreads();
    float inv = nrm[tx];
#pragma unroll
    for (int r = 0; r < 32; ++r)
        ptr[(size_t)(ty * 32 + r) * NPOS + n] = __float2half_rn(t[r] * inv);
}

// ---------------- kmean: warp per channel (fp16 in) ----------------
__global__ void kmean_k(const __half* __restrict__ kbase, float* __restrict__ km)
{
    int b = blockIdx.y;
    int wid = threadIdx.x >> 5, lane = threadIdx.x & 31;
    int d = blockIdx.x * 8 + wid;
    const __half2* kp = (const __half2*)(kbase + (size_t)b * QKVD * NPOS + (size_t)d * NPOS);
    float s = 0.f;
#pragma unroll 8
    for (int i = lane; i < NPOS / 2; i += 32) {
        float2 v = __half22float2(kp[i]);
        s += v.x + v.y;
    }
#pragma unroll
    for (int o = 16; o > 0; o >>= 1) s += __shfl_xor_sync(0xFFFFFFFFu, s, o);
    if (lane == 0) km[b * DIM + d] = s * (1.f / (float)NPOS);
}

// ---------------- z[b][n] = kmean · q[:, n] + eps ----------------
__global__ void zcalc(const __half* __restrict__ q, const float* __restrict__ km, float* __restrict__ zo)
{
    __shared__ float kms[256];
    int b = blockIdx.y;
    int tid = threadIdx.x;
    kms[tid] = km[b * DIM + tid];
    __syncthreads();
    int n = blockIdx.x * 256 + tid;
    const __half* qp = q + (size_t)b * QKVD * NPOS + n;
    float s = 0.f;
#pragma unroll 4
    for (int d = 0; d < 256; ++d) s += kms[d] * __half2float(qp[(size_t)d * NPOS]);
    zo[(size_t)b * NPOS + n] = s + EPSF;
}

// ---------------- vkt reduce (8 chunks) + 1/N -> fp16 ----------------
__global__ void vkt_reduce(const float* __restrict__ part, __half* __restrict__ vkT)
{
    int idx = blockIdx.x * 256 + threadIdx.x;
    int b = idx >> 16, ij = idx & 65535;
    float s = 0.f;
#pragma unroll
    for (int c = 0; c < 8; ++c) s += part[(size_t)(b * 8 + c) * 65536 + ij];
    vkT[idx] = __float2half_rn(s * (1.f / (float)NPOS));
}

// ---------------- depthwise 5x5 on fp16 v slice -> fp32 dw ----------------
__global__ void dwconv_kernel(const __half* __restrict__ vbase, const float* __restrict__ w,
                              const float* __restrict__ bias, float* __restrict__ dw)
{
    int ch = blockIdx.x, b = blockIdx.y;
    const __half* vp = vbase + (size_t)b * QKVD * NPOS + (size_t)ch * NPOS;
    __shared__ float sm[68][68];
    __shared__ float ws[25];
    int tid = threadIdx.x;
    if (tid < 25) ws[tid] = w[ch * 25 + tid];
    for (int idx = tid; idx < 68 * 68; idx += 256) {
        int r = idx / 68, c = idx % 68;
        int gr = r - 2, gc = c - 2;
        sm[r][c] = (gr >= 0 && gr < HH && gc >= 0 && gc < WW) ? __half2float(vp[gr * WW + gc]) : 0.f;
    }
    __syncthreads();
    float bv = bias[ch];
    for (int p = tid; p < NPOS; p += 256) {
        int py = p >> 6, px = p & 63;
        float acc = bv;
#pragma unroll
        for (int ky = 0; ky < 5; ++ky)
#pragma unroll
            for (int kx = 0; kx < 5; ++kx)
                acc += sm[py + ky][px + kx] * ws[ky * 5 + kx];
        dw[((size_t)b * DIM + ch) * NPOS + p] = acc;
    }
}

// ---------------- host ----------------
extern "C" void kernel_launch(void* const* d_in, const int* in_sizes, int n_in,
                              void* d_out, int out_size)
{
    const float* x      = (const float*)d_in[0];
    const float* qkv_w  = (const float*)d_in[1];
    const float* qkv_b  = (const float*)d_in[2];
    const float* dwc_w  = (const float*)d_in[3];
    const float* dwc_b  = (const float*)d_in[4];
    const float* norm_w = (const float*)d_in[5];
    const float* proj_w = (const float*)d_in[6];
    const float* proj_b = (const float*)d_in[7];
    float* out = (float*)d_out;

    __half *p_xh, *p_qkv, *p_vkT, *p_y, *p_qw, *p_pw;
    float *p_part, *p_dw, *p_z, *p_km;
    cudaGetSymbolAddress((void**)&p_xh, g_xh);
    cudaGetSymbolAddress((void**)&p_qkv, g_qkv);
    cudaGetSymbolAddress((void**)&p_vkT, g_vkT);
    cudaGetSymbolAddress((void**)&p_part, g_part);
    cudaGetSymbolAddress((void**)&p_dw, g_dw);
    cudaGetSymbolAddress((void**)&p_y, g_y);
    cudaGetSymbolAddress((void**)&p_z, g_z);
    cudaGetSymbolAddress((void**)&p_km, g_kmean);
    cudaGetSymbolAddress((void**)&p_qw, g_qw);
    cudaGetSymbolAddress((void**)&p_pw, g_pw);

    const size_t kOff = (size_t)256 * NPOS, vOff = (size_t)512 * NPOS;

    const int SMEM_G = 6 * AST;                                   // 36864
    const int SMEM_A = EPI_BYTES + (256 + 4 * 132 + 128) * 4;     // ~53.6 KB
    cudaFuncSetAttribute(hgemm, cudaFuncAttributeMaxDynamicSharedMemorySize, SMEM_G);
    cudaFuncSetAttribute(attn_fused, cudaFuncAttributeMaxDynamicSharedMemorySize, SMEM_A);

    // 1-3. convert x and weights to fp16
    round_copy_h<<<(BATCH * DIM * NPOS + 255) / 256, 256>>>(x, p_xh, BATCH * DIM * NPOS);
    round_copy_h<<<(QKVD * DIM + 255) / 256, 256>>>(qkv_w, p_qw, QKVD * DIM);
    round_copy_h<<<(DIM * DIM + 255) / 256, 256>>>(proj_w, p_pw, DIM * DIM);
    // 4. qkv[768][n] = qkv_w · x  (B trans), fp16 out, bias per-row
    hgemm<<<dim3(NPOS / 128, QKVD / 128, BATCH), 256, SMEM_G>>>(
        p_qw, p_xh, qkv_b, p_qkv, 256, DIM, NPOS, NPOS,
        0LL, (long long)DIM * NPOS, (long long)QKVD * NPOS, 1, 2, 1, 1);
    // 5. featmap q,k in place
    featmap_kernel<<<dim3(NPOS / 32, 2, BATCH), dim3(32, 8)>>>(p_qkv);
    // 6,7. kmean, z
    kmean_k<<<dim3(DIM / 8, BATCH), 256>>>(p_qkv + kOff, p_km);
    zcalc<<<dim3(NPOS / 256, BATCH), 256>>>(p_qkv, p_km, p_z);
    // 8,9. vkT = v · k^T / N  (split-K x8), fp32 partials -> fp16
    hgemm<<<dim3(2, 2, BATCH * 8), 256, SMEM_G>>>(
        p_qkv + vOff, p_qkv + kOff, nullptr, p_part, 512, NPOS, NPOS, DIM,
        (long long)QKVD * NPOS, (long long)QKVD * NPOS, (long long)DIM * DIM, 8, 0, 0, 0);
    vkt_reduce<<<dim3(BATCH * DIM * DIM / 256), 256>>>(p_part, p_vkT);
    // 10. depthwise conv on v
    dwconv_kernel<<<dim3(DIM, BATCH), 256>>>(p_qkv + vOff, dwc_w, dwc_b, p_dw);
    // 11. fused attn -> y[d][n] fp16
    attn_fused<<<dim3(NPOS / 128, 1, BATCH), 512, SMEM_A>>>(p_vkT, p_qkv, p_z, p_dw, norm_w, p_y);
    // 12. out[c][n] = proj_w · y + proj_b  (B trans), fp32 out
    hgemm<<<dim3(NPOS / 128, DIM / 128, BATCH), 256, SMEM_G>>>(
        p_pw, p_y, proj_b, out, 256, DIM, NPOS, NPOS,
        0LL, (long long)DIM * NPOS, (long long)DIM * NPOS, 1, 2, 1, 0);
}

// round 14
// speedup vs baseline: 7.2141x; 1.0640x over previous
#include <cuda_runtime.h>
#include <cuda_fp16.h>
#include <cstdint>

#define BATCH 16
#define DIM   256
#define NPOS  4096
#define QKVD  768
#define HH    64
#define WW    64
#define EPSF  1e-5f

// ---------------- scratch ----------------
__device__ __half g_xh [(size_t)BATCH * DIM * NPOS];    // fp16 x [b][c][n]
__device__ __half g_qkv[(size_t)BATCH * QKVD * NPOS];   // fp16 [b][768][n]
__device__ __half g_vkT[(size_t)BATCH * DIM * DIM];
__device__ float  g_part[(size_t)BATCH * 8 * DIM * DIM];
__device__ __half g_dw [(size_t)BATCH * DIM * NPOS];
__device__ __half g_y  [(size_t)BATCH * DIM * NPOS];
__device__ float  g_z  [(size_t)BATCH * NPOS];
__device__ float  g_kmean[BATCH * DIM];
__device__ __half g_qw[QKVD * DIM];
__device__ __half g_pw[DIM * DIM];

__device__ __forceinline__ void cp16(uint32_t smem, const void* g) {
    asm volatile("cp.async.cg.shared.global [%0], [%1], 16;" :: "r"(smem), "l"(g));
}
#define CP_COMMIT() asm volatile("cp.async.commit_group;" ::: "memory")
#define CP_WAIT1()  asm volatile("cp.async.wait_group 1;" ::: "memory")

__device__ __forceinline__ void ldsm_x4(uint32_t& r0, uint32_t& r1, uint32_t& r2, uint32_t& r3,
                                        uint32_t addr) {
    asm volatile("ldmatrix.sync.aligned.m8n8.x4.shared.b16 {%0,%1,%2,%3}, [%4];"
                 : "=r"(r0), "=r"(r1), "=r"(r2), "=r"(r3) : "r"(addr));
}
__device__ __forceinline__ void ldsm_x4_t(uint32_t& r0, uint32_t& r1, uint32_t& r2, uint32_t& r3,
                                          uint32_t addr) {
    asm volatile("ldmatrix.sync.aligned.m8n8.x4.trans.shared.b16 {%0,%1,%2,%3}, [%4];"
                 : "=r"(r0), "=r"(r1), "=r"(r2), "=r"(r3) : "r"(addr));
}

#define MMA_F16(acc, a0, a1, a2, a3, b0, b1) \
    asm volatile("mma.sync.aligned.m16n8k16.row.col.f32.f16.f16.f32 " \
                 "{%0,%1,%2,%3}, {%4,%5,%6,%7}, {%8,%9}, {%0,%1,%2,%3};" \
                 : "+f"((acc)[0]), "+f"((acc)[1]), "+f"((acc)[2]), "+f"((acc)[3]) \
                 : "r"(a0), "r"(a1), "r"(a2), "r"(a3), "r"(b0), "r"(b1))

// A-frag lane offset (80B row stride, [rows][k32])
__device__ __forceinline__ uint32_t ldsmA_off(int lane) {
    int row = ((lane >> 3) & 1) * 8 + (lane & 7);
    return (uint32_t)(row * 80 + (lane >> 4) * 16);
}
// B-frag (non-trans, [n][k32], 80B stride)
__device__ __forceinline__ uint32_t ldsmBn_off(int lane) {
    int row = ((lane >> 4) & 1) * 8 + (lane & 7);
    return (uint32_t)(row * 80 + ((lane >> 3) & 1) * 16);
}
// B-frag (trans, [k32][n], 272B stride)
__device__ __forceinline__ uint32_t ldsmBt_off(int lane) {
    int krow = ((lane >> 3) & 1) * 8 + (lane & 7);
    return (uint32_t)(krow * 272 + ((lane >> 4) & 1) * 16);
}

// ---------------- fp16 mma GEMM, k32 stages, cp.async 3-stage ----------------
#define AST 10240   // stage bytes: 128 rows * 80B
__global__ __launch_bounds__(256)
void hgemm(const __half* __restrict__ A, const __half* __restrict__ B,
           const float* __restrict__ bias, void* __restrict__ Cv,
           int K, int ldA, int ldB, int ldC,
           long long aStride, long long bStride, long long cStride,
           int kChunks, int biasMode, int bTrans, int outHalf)
{
    extern __shared__ char smc[];

    int z = blockIdx.z;
    int b = z / kChunks, chunk = z - b * kChunks;
    int kStart = chunk * K;
    int m0 = blockIdx.y * 128, n0 = blockIdx.x * 128;
    const __half* Ab = A + (size_t)b * aStride + (size_t)m0 * ldA + kStart;

    int tid = threadIdx.x;
    int lane = tid & 31, wid = tid >> 5;
    int g = lane >> 2, tig = lane & 3;
    int warp_m = (wid & 1) * 64, warp_n = (wid >> 1) * 32;

    uint32_t sbase;
    asm("{ .reg .u64 t; cvta.to.shared.u64 t, %1; cvt.u32.u64 %0, t; }" : "=r"(sbase) : "l"(smc));
    uint32_t sA = sbase, sB = sbase + 3 * AST;

    // A loader: 512 16B-chunks (128 rows x 64B), 2 per thread
    int ac0 = tid, ac1 = tid + 256;
    int ar0 = ac0 >> 2, akc0 = ac0 & 3;
    int ar1 = ac1 >> 2, akc1 = ac1 & 3;
    uint32_t aoff0 = (uint32_t)(ar0 * 80 + akc0 * 16);
    uint32_t aoff1 = (uint32_t)(ar1 * 80 + akc1 * 16);
    const __half* ag0 = Ab + (size_t)ar0 * ldA + akc0 * 8;
    const __half* ag1 = Ab + (size_t)ar1 * ldA + akc1 * 8;

    // B loaders
    const __half* bg0 = nullptr; const __half* bg1 = nullptr;
    const __half* btg = nullptr;
    uint32_t boff0 = 0, boff1 = 0;
    int bkr0 = 0, bnc0 = 0, bkr1 = 0, bnc1 = 0;
    if (!bTrans) {
        const __half* Bb = B + (size_t)b * bStride + (size_t)n0 * ldB + kStart;
        bg0 = Bb + (size_t)ar0 * ldB + akc0 * 8;
        bg1 = Bb + (size_t)ar1 * ldB + akc1 * 8;
        boff0 = aoff0; boff1 = aoff1;
    } else {
        btg = B + (size_t)b * bStride + (size_t)kStart * ldB + n0;
        bkr0 = ac0 >> 4; bnc0 = ac0 & 15;
        bkr1 = ac1 >> 4; bnc1 = ac1 & 15;
        boff0 = (uint32_t)(bkr0 * 272 + bnc0 * 16);
        boff1 = (uint32_t)(bkr1 * 272 + bnc1 * 16);
    }

    uint32_t aF = ldsmA_off(lane) + (uint32_t)warp_m * 80;
    uint32_t bFn = ldsmBn_off(lane) + (uint32_t)warp_n * 80;
    uint32_t bFt = ldsmBt_off(lane) + (uint32_t)warp_n * 2;

    int S = K >> 5;   // k32 stages

    float acc[4][4][4];
#pragma unroll
    for (int i = 0; i < 4; ++i)
#pragma unroll
        for (int j = 0; j < 4; ++j)
#pragma unroll
            for (int r = 0; r < 4; ++r) acc[i][j][r] = 0.f;

#pragma unroll
    for (int ps = 0; ps < 2; ++ps) {
        int kc = ps * 32;
        uint32_t so = ps * AST;
        cp16(sA + so + aoff0, ag0 + kc);
        cp16(sA + so + aoff1, ag1 + kc);
        if (!bTrans) {
            cp16(sB + so + boff0, bg0 + kc);
            cp16(sB + so + boff1, bg1 + kc);
        } else {
            cp16(sB + so + boff0, btg + (size_t)(kc + bkr0) * ldB + bnc0 * 8);
            cp16(sB + so + boff1, btg + (size_t)(kc + bkr1) * ldB + bnc1 * 8);
        }
        CP_COMMIT();
    }

    for (int s = 0; s < S; ++s) {
        CP_WAIT1();
        __syncthreads();
        if (s + 2 < S) {
            int buf2 = (s + 2) % 3;
            int kc = (s + 2) * 32;
            uint32_t so = buf2 * AST;
            cp16(sA + so + aoff0, ag0 + kc);
            cp16(sA + so + aoff1, ag1 + kc);
            if (!bTrans) {
                cp16(sB + so + boff0, bg0 + kc);
                cp16(sB + so + boff1, bg1 + kc);
            } else {
                cp16(sB + so + boff0, btg + (size_t)(kc + bkr0) * ldB + bnc0 * 8);
                cp16(sB + so + boff1, btg + (size_t)(kc + bkr1) * ldB + bnc1 * 8);
            }
        }
        CP_COMMIT();
        uint32_t stA = sA + (s % 3) * AST;
        uint32_t stB = sB + (s % 3) * AST;
#pragma unroll
        for (int h = 0; h < 2; ++h) {
            uint32_t af[4][4], bf[4][2];
#pragma unroll
            for (int i = 0; i < 4; ++i)
                ldsm_x4(af[i][0], af[i][1], af[i][2], af[i][3],
                        stA + aF + (uint32_t)(i * 16 * 80 + h * 32));
            if (!bTrans) {
#pragma unroll
                for (int jj = 0; jj < 2; ++jj)
                    ldsm_x4(bf[2 * jj][0], bf[2 * jj][1], bf[2 * jj + 1][0], bf[2 * jj + 1][1],
                            stB + bFn + (uint32_t)(jj * 16 * 80 + h * 32));
            } else {
#pragma unroll
                for (int jj = 0; jj < 2; ++jj)
                    ldsm_x4_t(bf[2 * jj][0], bf[2 * jj][1], bf[2 * jj + 1][0], bf[2 * jj + 1][1],
                              stB + bFt + (uint32_t)(jj * 32 + h * 16 * 272));
            }
#pragma unroll
            for (int i = 0; i < 4; ++i)
#pragma unroll
                for (int j = 0; j < 4; ++j)
                    MMA_F16(acc[i][j], af[i][0], af[i][1], af[i][2], af[i][3], bf[j][0], bf[j][1]);
        }
    }

    // epilogue
#pragma unroll
    for (int i = 0; i < 4; ++i) {
        int row0 = m0 + warp_m + i * 16 + g;
        float br0 = (biasMode == 2) ? bias[row0] : 0.f;
        float br1 = (biasMode == 2) ? bias[row0 + 8] : 0.f;
#pragma unroll
        for (int j = 0; j < 4; ++j) {
            int col = n0 + warp_n + j * 8 + tig * 2;
            if (outHalf) {
                __half* Ch = (__half*)Cv + (size_t)z * cStride;
                *(__half2*)&Ch[(size_t)row0 * ldC + col] =
                    __floats2half2_rn(acc[i][j][0] + br0, acc[i][j][1] + br0);
                *(__half2*)&Ch[(size_t)(row0 + 8) * ldC + col] =
                    __floats2half2_rn(acc[i][j][2] + br1, acc[i][j][3] + br1);
            } else {
                float* Cf = (float*)Cv + (size_t)z * cStride;
                *(float2*)&Cf[(size_t)row0 * ldC + col] =
                    make_float2(acc[i][j][0] + br0, acc[i][j][1] + br0);
                *(float2*)&Cf[(size_t)(row0 + 8) * ldC + col] =
                    make_float2(acc[i][j][2] + br1, acc[i][j][3] + br1);
            }
        }
    }
}

// ---------------- fused attn: y[d][n] = RMSNorm((vkT·q)/z)*nw + dw, fp16. 512 threads ----------------
#define AST2 20480   // 256 rows * 80B
#define BSTT 8704    // 32 k-rows * 272B
#define EPI_BYTES (3 * AST2 + 3 * BSTT)
__global__ __launch_bounds__(512)
void attn_fused(const __half* __restrict__ vkT, const __half* __restrict__ q,
                const float* __restrict__ zbuf, const __half* __restrict__ dw,
                const float* __restrict__ norm_w, __half* __restrict__ y)
{
    extern __shared__ char smc[];
    float* nw  = (float*)(smc + EPI_BYTES);
    float* ssq = nw + 256;
    float* rr  = ssq + 4 * 132;

    int b = blockIdx.z;
    int n0 = blockIdx.x * 128;
    const __half* Ab = vkT + (size_t)b * DIM * DIM;
    const __half* qg = q + (size_t)b * QKVD * NPOS + n0;
    const __half* dp = dw + (size_t)b * DIM * NPOS;
    __half* yp = y + (size_t)b * DIM * NPOS;

    int tid = threadIdx.x;
    int lane = tid & 31, wid = tid >> 5;
    int g = lane >> 2, tig = lane & 3;
    int warp_m = (wid & 3) * 64, warp_n = (wid >> 2) * 32;

    if (tid < 256) nw[tid] = norm_w[tid];

    uint32_t sbase;
    asm("{ .reg .u64 t; cvta.to.shared.u64 t, %1; cvt.u32.u64 %0, t; }" : "=r"(sbase) : "l"(smc));
    uint32_t sA = sbase, sB = sbase + 3 * AST2;

    // A loader: 1024 chunks (256 rows x 64B), 2 per thread
    int ac0 = tid, ac1 = tid + 512;
    int ar0 = ac0 >> 2, akc0 = ac0 & 3;
    int ar1 = ac1 >> 2, akc1 = ac1 & 3;
    uint32_t aoff0 = (uint32_t)(ar0 * 80 + akc0 * 16);
    uint32_t aoff1 = (uint32_t)(ar1 * 80 + akc1 * 16);
    // B loader: 512 chunks (32 k-rows x 256B), 1 per thread
    int bkr = tid >> 4, bnc = tid & 15;
    uint32_t boff = (uint32_t)(bkr * 272 + bnc * 16);

    uint32_t aF = ldsmA_off(lane) + (uint32_t)warp_m * 80;
    uint32_t bFt = ldsmBt_off(lane) + (uint32_t)warp_n * 2;

#pragma unroll
    for (int ps = 0; ps < 2; ++ps) {
        int kc = ps * 32;
        cp16(sA + ps * AST2 + aoff0, Ab + (size_t)ar0 * DIM + kc + akc0 * 8);
        cp16(sA + ps * AST2 + aoff1, Ab + (size_t)ar1 * DIM + kc + akc1 * 8);
        cp16(sB + ps * BSTT + boff, qg + (size_t)(kc + bkr) * NPOS + bnc * 8);
        CP_COMMIT();
    }

    float acc[4][4][4];
#pragma unroll
    for (int i = 0; i < 4; ++i)
#pragma unroll
        for (int j = 0; j < 4; ++j)
#pragma unroll
            for (int r = 0; r < 4; ++r) acc[i][j][r] = 0.f;

    const int S = 8;   // K=256, k32
    for (int s = 0; s < S; ++s) {
        CP_WAIT1();
        __syncthreads();
        if (s + 2 < S) {
            int buf2 = (s + 2) % 3;
            int kc = (s + 2) * 32;
            cp16(sA + buf2 * AST2 + aoff0, Ab + (size_t)ar0 * DIM + kc + akc0 * 8);
            cp16(sA + buf2 * AST2 + aoff1, Ab + (size_t)ar1 * DIM + kc + akc1 * 8);
            cp16(sB + buf2 * BSTT + boff, qg + (size_t)(kc + bkr) * NPOS + bnc * 8);
        }
        CP_COMMIT();
        uint32_t stA = sA + (s % 3) * AST2;
        uint32_t stB = sB + (s % 3) * BSTT;
#pragma unroll
        for (int h = 0; h < 2; ++h) {
            uint32_t af[4][4], bf[4][2];
#pragma unroll
            for (int i = 0; i < 4; ++i)
                ldsm_x4(af[i][0], af[i][1], af[i][2], af[i][3],
                        stA + aF + (uint32_t)(i * 16 * 80 + h * 32));
#pragma unroll
            for (int jj = 0; jj < 2; ++jj)
                ldsm_x4_t(bf[2 * jj][0], bf[2 * jj][1], bf[2 * jj + 1][0], bf[2 * jj + 1][1],
                          stB + bFt + (uint32_t)(jj * 32 + h * 16 * 272));
#pragma unroll
            for (int i = 0; i < 4; ++i)
#pragma unroll
                for (int j = 0; j < 4; ++j)
                    MMA_F16(acc[i][j], af[i][0], af[i][1], af[i][2], af[i][3], bf[j][0], bf[j][1]);
        }
    }

    // ---- fused epilogue ----
    float ss[8];
#pragma unroll
    for (int j = 0; j < 4; ++j) {
        int col = warp_n + j * 8 + tig * 2;
        float2 zv = *(const float2*)&zbuf[(size_t)b * NPOS + n0 + col];
        float iz0 = 1.f / zv.x, iz1 = 1.f / zv.y;
        float s0 = 0.f, s1 = 0.f;
#pragma unroll
        for (int i = 0; i < 4; ++i) {
            acc[i][j][0] *= iz0; acc[i][j][1] *= iz1;
            acc[i][j][2] *= iz0; acc[i][j][3] *= iz1;
            s0 += acc[i][j][0] * acc[i][j][0] + acc[i][j][2] * acc[i][j][2];
            s1 += acc[i][j][1] * acc[i][j][1] + acc[i][j][3] * acc[i][j][3];
        }
        ss[j * 2] = s0; ss[j * 2 + 1] = s1;
    }
#pragma unroll
    for (int o = 4; o <= 16; o <<= 1)
#pragma unroll
        for (int c = 0; c < 8; ++c) ss[c] += __shfl_xor_sync(0xFFFFFFFFu, ss[c], o);
    __syncthreads();
    if (g == 0) {
        int wm = wid & 3;
#pragma unroll
        for (int j = 0; j < 4; ++j) {
            int col = warp_n + j * 8 + tig * 2;
            ssq[wm * 132 + col] = ss[j * 2];
            ssq[wm * 132 + col + 1] = ss[j * 2 + 1];
        }
    }
    __syncthreads();
    if (tid < 128) {
        float s = ssq[tid] + ssq[132 + tid] + ssq[264 + tid] + ssq[396 + tid];
        rr[tid] = rsqrtf(s * (1.f / (float)DIM) + EPSF);
    }
    __syncthreads();
#pragma unroll
    for (int i = 0; i < 4; ++i) {
        int row0 = warp_m + i * 16 + g;
#pragma unroll
        for (int j = 0; j < 4; ++j) {
            int col = warp_n + j * 8 + tig * 2;
            float r0 = rr[col], r1 = rr[col + 1];
            float2 d0 = __half22float2(*(const __half2*)&dp[(size_t)row0 * NPOS + n0 + col]);
            float2 d1 = __half22float2(*(const __half2*)&dp[(size_t)(row0 + 8) * NPOS + n0 + col]);
            *(__half2*)&yp[(size_t)row0 * NPOS + n0 + col] =
                __floats2half2_rn(acc[i][j][0] * r0 * nw[row0] + d0.x,
                                  acc[i][j][1] * r1 * nw[row0] + d0.y);
            *(__half2*)&yp[(size_t)(row0 + 8) * NPOS + n0 + col] =
                __floats2half2_rn(acc[i][j][2] * r0 * nw[row0 + 8] + d1.x,
                                  acc[i][j][3] * r1 * nw[row0 + 8] + d1.y);
        }
    }
}

// ---------------- fp32 -> fp16 copy ----------------
__global__ void round_copy_h(const float* __restrict__ in, __half* __restrict__ out, int n)
{
    int i = blockIdx.x * 256 + threadIdx.x;
    if (i < n) out[i] = __float2half_rn(in[i]);
}

// ---------------- featmap in place on fp16 [d][n] slice ----------------
__global__ void featmap_kernel(__half* __restrict__ qkv)
{
    int b = blockIdx.z;
    __half* ptr = qkv + ((size_t)b * QKVD + (blockIdx.y ? 256 : 0)) * NPOS;
    int tx = threadIdx.x, ty = threadIdx.y;          // 32 x 8
    int n = blockIdx.x * 32 + tx;
    float t[32];
    float s = 0.f;
#pragma unroll
    for (int r = 0; r < 32; ++r) {
        float v = __half2float(ptr[(size_t)(ty * 32 + r) * NPOS + n]);
        v = fmaxf(v, 0.f) + EPSF;
        v = v * v;
        t[r] = v;
        s += v * v;
    }
    __shared__ float red[8][33];
    __shared__ float nrm[32];
    red[ty][tx] = s;
    __syncthreads();
    if (ty == 0) {
        float tot = 0.f;
#pragma unroll
        for (int k = 0; k < 8; ++k) tot += red[k][tx];
        nrm[tx] = 1.f / fmaxf(sqrtf(tot), 1e-12f);
    }
    __syncthreads();
    float inv = nrm[tx];
#pragma unroll
    for (int r = 0; r < 32; ++r)
        ptr[(size_t)(ty * 32 + r) * NPOS + n] = __float2half_rn(t[r] * inv);
}

// ---------------- kmean: warp per channel ----------------
__global__ void kmean_k(const __half* __restrict__ kbase, float* __restrict__ km)
{
    int b = blockIdx.y;
    int wid = threadIdx.x >> 5, lane = threadIdx.x & 31;
    int d = blockIdx.x * 8 + wid;
    const __half2* kp = (const __half2*)(kbase + (size_t)b * QKVD * NPOS + (size_t)d * NPOS);
    float s = 0.f;
#pragma unroll 8
    for (int i = lane; i < NPOS / 2; i += 32) {
        float2 v = __half22float2(kp[i]);
        s += v.x + v.y;
    }
#pragma unroll
    for (int o = 16; o > 0; o >>= 1) s += __shfl_xor_sync(0xFFFFFFFFu, s, o);
    if (lane == 0) km[b * DIM + d] = s * (1.f / (float)NPOS);
}

// ---------------- z[b][n] = kmean · q[:, n] + eps ----------------
__global__ void zcalc(const __half* __restrict__ q, const float* __restrict__ km, float* __restrict__ zo)
{
    __shared__ float kms[256];
    int b = blockIdx.y;
    int tid = threadIdx.x;
    kms[tid] = km[b * DIM + tid];
    __syncthreads();
    int n = blockIdx.x * 256 + tid;
    const __half* qp = q + (size_t)b * QKVD * NPOS + n;
    float s = 0.f;
#pragma unroll 4
    for (int d = 0; d < 256; ++d) s += kms[d] * __half2float(qp[(size_t)d * NPOS]);
    zo[(size_t)b * NPOS + n] = s + EPSF;
}

// ---------------- vkt reduce (8 chunks) + 1/N -> fp16 ----------------
__global__ void vkt_reduce(const float* __restrict__ part, __half* __restrict__ vkT)
{
    int idx = blockIdx.x * 256 + threadIdx.x;
    int b = idx >> 16, ij = idx & 65535;
    float s = 0.f;
#pragma unroll
    for (int c = 0; c < 8; ++c) s += part[(size_t)(b * 8 + c) * 65536 + ij];
    vkT[idx] = __float2half_rn(s * (1.f / (float)NPOS));
}

// ---------------- depthwise 5x5 on fp16 v slice -> fp16 dw ----------------
__global__ void dwconv_kernel(const __half* __restrict__ vbase, const float* __restrict__ w,
                              const float* __restrict__ bias, __half* __restrict__ dw)
{
    int ch = blockIdx.x, b = blockIdx.y;
    const __half* vp = vbase + (size_t)b * QKVD * NPOS + (size_t)ch * NPOS;
    __shared__ float sm[68][68];
    __shared__ float ws[25];
    int tid = threadIdx.x;
    if (tid < 25) ws[tid] = w[ch * 25 + tid];
    for (int idx = tid; idx < 68 * 68; idx += 256) {
        int r = idx / 68, c = idx % 68;
        int gr = r - 2, gc = c - 2;
        sm[r][c] = (gr >= 0 && gr < HH && gc >= 0 && gc < WW) ? __half2float(vp[gr * WW + gc]) : 0.f;
    }
    __syncthreads();
    float bv = bias[ch];
    for (int p = tid; p < NPOS; p += 256) {
        int py = p >> 6, px = p & 63;
        float acc = bv;
#pragma unroll
        for (int ky = 0; ky < 5; ++ky)
#pragma unroll
            for (int kx = 0; kx < 5; ++kx)
                acc += sm[py + ky][px + kx] * ws[ky * 5 + kx];
        dw[((size_t)b * DIM + ch) * NPOS + p] = __float2half_rn(acc);
    }
}

// ---------------- host ----------------
extern "C" void kernel_launch(void* const* d_in, const int* in_sizes, int n_in,
                              void* d_out, int out_size)
{
    const float* x      = (const float*)d_in[0];
    const float* qkv_w  = (const float*)d_in[1];
    const float* qkv_b  = (const float*)d_in[2];
    const float* dwc_w  = (const float*)d_in[3];
    const float* dwc_b  = (const float*)d_in[4];
    const float* norm_w = (const float*)d_in[5];
    const float* proj_w = (const float*)d_in[6];
    const float* proj_b = (const float*)d_in[7];
    float* out = (float*)d_out;

    __half *p_xh, *p_qkv, *p_vkT, *p_y, *p_qw, *p_pw, *p_dw;
    float *p_part, *p_z, *p_km;
    cudaGetSymbolAddress((void**)&p_xh, g_xh);
    cudaGetSymbolAddress((void**)&p_qkv, g_qkv);
    cudaGetSymbolAddress((void**)&p_vkT, g_vkT);
    cudaGetSymbolAddress((void**)&p_part, g_part);
    cudaGetSymbolAddress((void**)&p_dw, g_dw);
    cudaGetSymbolAddress((void**)&p_y, g_y);
    cudaGetSymbolAddress((void**)&p_z, g_z);
    cudaGetSymbolAddress((void**)&p_km, g_kmean);
    cudaGetSymbolAddress((void**)&p_qw, g_qw);
    cudaGetSymbolAddress((void**)&p_pw, g_pw);

    const size_t kOff = (size_t)256 * NPOS, vOff = (size_t)512 * NPOS;

    const int SMEM_G = 6 * AST;                                   // 61440
    const int SMEM_A = EPI_BYTES + (256 + 4 * 132 + 128) * 4;     // ~91 KB
    cudaFuncSetAttribute(hgemm, cudaFuncAttributeMaxDynamicSharedMemorySize, SMEM_G);
    cudaFuncSetAttribute(attn_fused, cudaFuncAttributeMaxDynamicSharedMemorySize, SMEM_A);

    // 1-3. convert x and weights to fp16
    round_copy_h<<<(BATCH * DIM * NPOS + 255) / 256, 256>>>(x, p_xh, BATCH * DIM * NPOS);
    round_copy_h<<<(QKVD * DIM + 255) / 256, 256>>>(qkv_w, p_qw, QKVD * DIM);
    round_copy_h<<<(DIM * DIM + 255) / 256, 256>>>(proj_w, p_pw, DIM * DIM);
    // 4. qkv[768][n] = qkv_w · x  (B trans), fp16 out, bias per-row
    hgemm<<<dim3(NPOS / 128, QKVD / 128, BATCH), 256, SMEM_G>>>(
        p_qw, p_xh, qkv_b, p_qkv, 256, DIM, NPOS, NPOS,
        0LL, (long long)DIM * NPOS, (long long)QKVD * NPOS, 1, 2, 1, 1);
    // 5. featmap q,k in place
    featmap_kernel<<<dim3(NPOS / 32, 2, BATCH), dim3(32, 8)>>>(p_qkv);
    // 6,7. kmean, z
    kmean_k<<<dim3(DIM / 8, BATCH), 256>>>(p_qkv + kOff, p_km);
    zcalc<<<dim3(NPOS / 256, BATCH), 256>>>(p_qkv, p_km, p_z);
    // 8,9. vkT = v · k^T / N  (split-K x8), fp32 partials -> fp16
    hgemm<<<dim3(2, 2, BATCH * 8), 256, SMEM_G>>>(
        p_qkv + vOff, p_qkv + kOff, nullptr, p_part, 512, NPOS, NPOS, DIM,
        (long long)QKVD * NPOS, (long long)QKVD * NPOS, (long long)DIM * DIM, 8, 0, 0, 0);
    vkt_reduce<<<dim3(BATCH * DIM * DIM / 256), 256>>>(p_part, p_vkT);
    // 10. depthwise conv on v -> fp16 dw
    dwconv_kernel<<<dim3(DIM, BATCH), 256>>>(p_qkv + vOff, dwc_w, dwc_b, p_dw);
    // 11. fused attn -> y[d][n] fp16
    attn_fused<<<dim3(NPOS / 128, 1, BATCH), 512, SMEM_A>>>(p_vkT, p_qkv, p_z, p_dw, norm_w, p_y);
    // 12. out[c][n] = proj_w · y + proj_b  (B trans), fp32 out
    hgemm<<<dim3(NPOS / 128, DIM / 128, BATCH), 256, SMEM_G>>>(
        p_pw, p_y, proj_b, out, 256, DIM, NPOS, NPOS,
        0LL, (long long)DIM * NPOS, (long long)DIM * NPOS, 1, 2, 1, 0);
}